// round 1
// baseline (speedup 1.0000x reference)
#include <cuda_runtime.h>
#include <cuda_bf16.h>
#include <cstdint>

// ---------------------------------------------------------------------------
// ContrastiveLoss: fused sim/exp/row-sum kernel + finalize reduction.
//   sums_kernel: grid (64 row-blocks, 4 col-splits), 256 thr, 8x8 microtiles.
//                A-tile (prescaled by log2e/T) resident in smem for the block;
//                B-tiles streamed. exp via raw ex2.approx.ftz (MUFU).
//   finalize_kernel: per-row loss + mean over valid rows.
// ---------------------------------------------------------------------------

#define N_ROWS 8192
#define DIM    128
#define BM     128
#define BN     128
#define NSPLIT 4
#define COLS_PER_SPLIT (N_ROWS / NSPLIT)   // 2048
#define NTILES (COLS_PER_SPLIT / BN)       // 16
#define THREADS 256
#define TM 8
#define TN 8
#define APAD 4
#define LDA (BM + APAD)                    // 132 floats, 16B-aligned row stride
#define LDB (BN + APAD)

// fold 1/temperature and log2(e) into A so exp(sim/T) == exp2(dot)
#define SCALE_LOG2E_OVER_T 20.60992915555662f   // log2(e)/0.07

__device__ float g_pos[NSPLIT][N_ROWS];
__device__ float g_tot[NSPLIT][N_ROWS];

__device__ __forceinline__ float ex2f(float x) {
    float y;
    asm("ex2.approx.ftz.f32 %0, %1;" : "=f"(y) : "f"(x));
    return y;
}

__device__ __forceinline__ int get_label(const void* p, int i, int is64) {
    if (is64) return (int)(((const long long*)p)[i]);
    return ((const int*)p)[i];
}

extern __shared__ float smem_dyn[];

__global__ void __launch_bounds__(THREADS, 1)
contrastive_sums_kernel(const float* __restrict__ emb,
                        const void* __restrict__ labels_raw)
{
    float* As = smem_dyn;               // [DIM][LDA] k-major, prescaled
    float* Bs = smem_dyn + DIM * LDA;   // [DIM][LDB] k-major
    __shared__ int cl_s[BN];
    __shared__ int flag_s;

    const int tid = threadIdx.x;
    const int row0 = blockIdx.x * BM;
    const int split = blockIdx.y;

    // --- detect label dtype layout (int64 -> all odd int32 words are 0) ---
    if (tid == 0) {
        const int* li = (const int*)labels_raw;
        int is64 = 1;
        #pragma unroll 4
        for (int i = 0; i < 64; i++) {
            if (li[2 * i + 1] != 0) { is64 = 0; break; }
        }
        flag_s = is64;
    }
    __syncthreads();
    const int is64 = flag_s;

    // --- load A tile once (k-major transpose, prescaled). m-fast mapping:
    //     consecutive threads -> consecutive m -> conflict-free STS.
    {
        const float4* e4 = (const float4*)emb;
        #pragma unroll
        for (int it = 0; it < (BM * DIM / 4) / THREADS; ++it) {
            int f = tid + it * THREADS;
            int m = f & (BM - 1);
            int kc = f >> 7;                     // float4 chunk index 0..31
            float4 v = e4[(size_t)(row0 + m) * (DIM / 4) + kc];
            int k = kc * 4;
            As[(k + 0) * LDA + m] = v.x * SCALE_LOG2E_OVER_T;
            As[(k + 1) * LDA + m] = v.y * SCALE_LOG2E_OVER_T;
            As[(k + 2) * LDA + m] = v.z * SCALE_LOG2E_OVER_T;
            As[(k + 3) * LDA + m] = v.w * SCALE_LOG2E_OVER_T;
        }
    }

    const int tx = tid & 15;
    const int ty = tid >> 4;
    const int r0 = ty * TM;       // local row base
    const int c0 = tx * TN;       // local col base within tile

    int rlab[TM];
    int grow[TM];
    #pragma unroll
    for (int i = 0; i < TM; i++) {
        grow[i] = row0 + r0 + i;
        rlab[i] = get_label(labels_raw, grow[i], is64);
    }

    float tot[TM], pos[TM];
    #pragma unroll
    for (int i = 0; i < TM; i++) { tot[i] = 0.f; pos[i] = 0.f; }

    for (int t = 0; t < NTILES; ++t) {
        const int col0 = split * COLS_PER_SPLIT + t * BN;

        __syncthreads();   // previous tile fully consumed
        // --- load B tile (k-major transpose) + column labels ---
        {
            const float4* e4 = (const float4*)emb;
            #pragma unroll
            for (int it = 0; it < (BN * DIM / 4) / THREADS; ++it) {
                int f = tid + it * THREADS;
                int n = f & (BN - 1);
                int kc = f >> 7;
                float4 v = e4[(size_t)(col0 + n) * (DIM / 4) + kc];
                int k = kc * 4;
                Bs[(k + 0) * LDB + n] = v.x;
                Bs[(k + 1) * LDB + n] = v.y;
                Bs[(k + 2) * LDB + n] = v.z;
                Bs[(k + 3) * LDB + n] = v.w;
            }
            if (tid < BN) cl_s[tid] = get_label(labels_raw, col0 + tid, is64);
        }
        __syncthreads();

        // --- GEMM microtile ---
        float acc[TM][TN];
        #pragma unroll
        for (int i = 0; i < TM; i++)
            #pragma unroll
            for (int j = 0; j < TN; j++) acc[i][j] = 0.f;

        #pragma unroll 4
        for (int k = 0; k < DIM; ++k) {
            float4 a0 = *(const float4*)&As[k * LDA + r0];
            float4 a1 = *(const float4*)&As[k * LDA + r0 + 4];
            float4 b0 = *(const float4*)&Bs[k * LDB + c0];
            float4 b1 = *(const float4*)&Bs[k * LDB + c0 + 4];
            float a[TM] = {a0.x, a0.y, a0.z, a0.w, a1.x, a1.y, a1.z, a1.w};
            float b[TN] = {b0.x, b0.y, b0.z, b0.w, b1.x, b1.y, b1.z, b1.w};
            #pragma unroll
            for (int i = 0; i < TM; i++)
                #pragma unroll
                for (int j = 0; j < TN; j++)
                    acc[i][j] += a[i] * b[j];
        }

        // --- exp + masked accumulate ---
        int cls[TN], gcol[TN];
        #pragma unroll
        for (int j = 0; j < TN; j++) {
            gcol[j] = col0 + c0 + j;
            cls[j] = cl_s[c0 + j];
        }
        #pragma unroll
        for (int i = 0; i < TM; i++) {
            const int rl = rlab[i];
            const int gr = grow[i];
            #pragma unroll
            for (int j = 0; j < TN; j++) {
                float e = ex2f(acc[i][j]);
                e = (gcol[j] == gr) ? 0.f : e;      // off-diagonal mask
                tot[i] += e;
                pos[i] += (cls[j] == rl) ? e : 0.f; // same-label mask
            }
        }
    }

    // --- cross-thread (tx) reduction of row partials, via smem (reuse As) ---
    __syncthreads();
    float* red = smem_dyn;   // [BM][17]
    #pragma unroll
    for (int i = 0; i < TM; i++) red[(r0 + i) * 17 + tx] = tot[i];
    __syncthreads();
    if (tid < BM) {
        float s = 0.f;
        #pragma unroll
        for (int u = 0; u < 16; u++) s += red[tid * 17 + u];
        g_tot[split][row0 + tid] = s;
    }
    __syncthreads();
    #pragma unroll
    for (int i = 0; i < TM; i++) red[(r0 + i) * 17 + tx] = pos[i];
    __syncthreads();
    if (tid < BM) {
        float s = 0.f;
        #pragma unroll
        for (int u = 0; u < 16; u++) s += red[tid * 17 + u];
        g_pos[split][row0 + tid] = s;
    }
}

__global__ void __launch_bounds__(256)
contrastive_finalize_kernel(float* __restrict__ out)
{
    __shared__ double ssum[256];
    __shared__ int scnt[256];
    const int tid = threadIdx.x;

    double lsum = 0.0;
    int cnt = 0;
    for (int i = tid; i < N_ROWS; i += 256) {
        float p = 0.f, tt = 0.f;
        #pragma unroll
        for (int s = 0; s < NSPLIT; s++) { p += g_pos[s][i]; tt += g_tot[s][i]; }
        if (p > 0.f) {
            float loss = -logf(p / (tt + 1e-8f) + 1e-8f);
            lsum += (double)loss;
            cnt++;
        }
    }
    ssum[tid] = lsum;
    scnt[tid] = cnt;
    __syncthreads();
    for (int s = 128; s > 0; s >>= 1) {
        if (tid < s) {
            ssum[tid] += ssum[tid + s];
            scnt[tid] += scnt[tid + s];
        }
        __syncthreads();
    }
    if (tid == 0) {
        int c = scnt[0];
        float mean = (c > 0) ? (float)(ssum[0] / (double)(c > 1 ? c : 1)) : 0.0f;
        out[0] = mean;
    }
}

extern "C" void kernel_launch(void* const* d_in, const int* in_sizes, int n_in,
                              void* d_out, int out_size)
{
    const float* emb = (const float*)d_in[0];
    const void* labels = d_in[1];
    float* out = (float*)d_out;

    const size_t smem_bytes = (size_t)2 * DIM * LDA * sizeof(float);  // 135168
    cudaFuncSetAttribute(contrastive_sums_kernel,
                         cudaFuncAttributeMaxDynamicSharedMemorySize,
                         (int)smem_bytes);

    dim3 grid(N_ROWS / BM, NSPLIT);
    contrastive_sums_kernel<<<grid, THREADS, smem_bytes>>>(emb, labels);
    contrastive_finalize_kernel<<<1, 256>>>(out);
}

// round 3
// speedup vs baseline: 3.1829x; 3.1829x over previous
#include <cuda_runtime.h>
#include <cuda_fp16.h>
#include <cstdint>

// ============================================================================
// ContrastiveLoss via mma.sync fp16 hi/lo-split GEMM (fp32-accurate).
// (tcgen05 is unavailable: harness PTX target is compute_103, not 103a.)
//   convert_kernel : emb fp32 -> prescaled fp16 hi/lo planes (row-major)
//   mma kernel     : 128 CTAs (64 row-blocks x 2 col-splits), 8 warps,
//                    warp tile 64x32, m16n8k16 HMMA, acc in registers,
//                    epilogue = ex2.approx + masked row sums
//   finalize1/2    : per-row loss + mean
// ============================================================================

#define N_ROWS 8192
#define DIM    128
#define BM     128
#define BN     128
#define NSPLIT 2
#define COLS_PER_SPLIT (N_ROWS / NSPLIT)   // 4096
#define NTILES (COLS_PER_SPLIT / BN)       // 32
#define THREADS 256
#define PLANE  32768                       // one 128x128 fp16 plane in smem

// sqrt(log2(e)/0.07): folded into BOTH operands so acc == (log2e/T) * dot
#define SQRT_SCALE 4.53981642f

// ---------------------------------------------------------------------------
// device scratch
// ---------------------------------------------------------------------------
__device__ float g_pos[NSPLIT][N_ROWS];
__device__ float g_tot[NSPLIT][N_ROWS];
__device__ float g_part[2][32];
__device__ __align__(16) __half g_hi[N_ROWS * DIM];
__device__ __align__(16) __half g_lo[N_ROWS * DIM];

// ---------------------------------------------------------------------------
// helpers
// ---------------------------------------------------------------------------
__device__ __forceinline__ uint32_t smem_u32(const void* p) {
    uint32_t a;
    asm("{ .reg .u64 t; cvta.to.shared.u64 t, %1; cvt.u32.u64 %0, t; }"
        : "=r"(a) : "l"(p));
    return a;
}

__device__ __forceinline__ float ex2f(float x) {
    float y;
    asm("ex2.approx.ftz.f32 %0, %1;" : "=f"(y) : "f"(x));
    return y;
}

__device__ __forceinline__ void cp16(uint32_t dst, const void* src) {
    asm volatile("cp.async.cg.shared.global [%0], [%1], 16;"
                 :: "r"(dst), "l"(src) : "memory");
}
#define CP_COMMIT() asm volatile("cp.async.commit_group;" ::: "memory")
#define CP_WAIT1()  asm volatile("cp.async.wait_group 1;" ::: "memory")

__device__ __forceinline__ void ldsm4(uint32_t& r0, uint32_t& r1,
                                      uint32_t& r2, uint32_t& r3, uint32_t a) {
    asm volatile("ldmatrix.sync.aligned.m8n8.x4.shared.b16 {%0,%1,%2,%3}, [%4];"
                 : "=r"(r0), "=r"(r1), "=r"(r2), "=r"(r3) : "r"(a));
}

__device__ __forceinline__ void mma16816(float& d0, float& d1, float& d2, float& d3,
                                         uint32_t a0, uint32_t a1, uint32_t a2, uint32_t a3,
                                         uint32_t b0, uint32_t b1) {
    asm volatile(
        "mma.sync.aligned.m16n8k16.row.col.f32.f16.f16.f32 "
        "{%0,%1,%2,%3}, {%4,%5,%6,%7}, {%8,%9}, {%0,%1,%2,%3};"
        : "+f"(d0), "+f"(d1), "+f"(d2), "+f"(d3)
        : "r"(a0), "r"(a1), "r"(a2), "r"(a3), "r"(b0), "r"(b1));
}

__device__ __forceinline__ int get_label(const void* p, int i, int is64) {
    if (is64) return (int)(((const long long*)p)[i]);
    return ((const int*)p)[i];
}

// smem tile addressing: 128 rows x 256B; 16B chunk c16 swizzled by row&7
__device__ __forceinline__ uint32_t tile_addr(uint32_t base, int row, int c16) {
    return base + (uint32_t)row * 256u + (uint32_t)(((c16 ^ (row & 7)) << 4));
}

// ---------------------------------------------------------------------------
// convert: fp32 emb -> prescaled fp16 hi/lo planes, row-major
// ---------------------------------------------------------------------------
__global__ void __launch_bounds__(256)
convert_kernel(const float* __restrict__ emb)
{
    int f = blockIdx.x * 256 + threadIdx.x;   // 131072 chunks of 8 elements
    int r = f >> 4;
    int c8 = f & 15;
    const float4* src = (const float4*)(emb + (size_t)r * DIM + c8 * 8);
    float4 v0 = src[0], v1 = src[1];
    float a[8] = {v0.x, v0.y, v0.z, v0.w, v1.x, v1.y, v1.z, v1.w};

    uint32_t hi[4], lo[4];
    #pragma unroll
    for (int p = 0; p < 4; p++) {
        float x0 = a[2 * p] * SQRT_SCALE;
        float x1 = a[2 * p + 1] * SQRT_SCALE;
        __half h0 = __float2half_rn(x0);
        __half h1 = __float2half_rn(x1);
        __half l0 = __float2half_rn(x0 - __half2float(h0));
        __half l1 = __float2half_rn(x1 - __half2float(h1));
        hi[p] = (uint32_t)__half_as_ushort(h0) | ((uint32_t)__half_as_ushort(h1) << 16);
        lo[p] = (uint32_t)__half_as_ushort(l0) | ((uint32_t)__half_as_ushort(l1) << 16);
    }
    size_t off = (size_t)r * DIM + c8 * 8;
    *(uint4*)(g_hi + off) = make_uint4(hi[0], hi[1], hi[2], hi[3]);
    *(uint4*)(g_lo + off) = make_uint4(lo[0], lo[1], lo[2], lo[3]);
}

// ---------------------------------------------------------------------------
// main MMA kernel
// ---------------------------------------------------------------------------
extern __shared__ __align__(16) char smem_dyn_c[];

// copy one 128-row hi+lo tile pair (global rows grow0..+127) into smem image
__device__ __forceinline__ void stage_tile(uint32_t base, int grow0, int tid) {
    #pragma unroll
    for (int i = 0; i < 16; i++) {
        int f = tid + i * THREADS;          // 0..4095
        int plane = f >> 11;
        int idx = f & 2047;
        int row = idx >> 4;
        int c16 = idx & 15;
        const __half* gsrc = (plane ? g_lo : g_hi);
        uint32_t dst = tile_addr(base + plane * PLANE, row, c16);
        cp16(dst, gsrc + (size_t)(grow0 + row) * DIM + c16 * 8);
    }
}

__global__ void __launch_bounds__(THREADS, 1)
contrastive_mma_kernel(const void* __restrict__ labels_raw)
{
    __shared__ int s_cl[2][BN];
    __shared__ int s_flag;
    __shared__ float s_red[2][BM][4];

    const int tid = threadIdx.x;
    const int lane = tid & 31;
    const int wid = tid >> 5;
    const int rb = blockIdx.x;
    const int split = blockIdx.y;
    const int row0 = rb * BM;

    uint32_t sbase = (smem_u32(smem_dyn_c) + 1023u) & ~1023u;
    const uint32_t Abase = sbase;
    const uint32_t Bbuf0 = sbase + 2u * PLANE;
    const uint32_t Bbuf1 = sbase + 4u * PLANE;

    if (tid == 0) {
        const int* li = (const int*)labels_raw;
        int is64 = 1;
        for (int i = 0; i < 64; i++)
            if (li[2 * i + 1] != 0) { is64 = 0; break; }
        s_flag = is64;
    }
    __syncthreads();
    const int is64 = s_flag;

    const int wm = wid >> 2;       // 0..1
    const int wn = wid & 3;        // 0..3
    const int m0 = wm * 64;
    const int n0 = wn * 32;
    const int g = lane >> 2;
    const int tig = lane & 3;

    // row labels for this thread's 8 accumulator rows
    int rl[8];
    #pragma unroll
    for (int mf = 0; mf < 4; mf++) {
        rl[mf * 2]     = get_label(labels_raw, row0 + m0 + mf * 16 + g, is64);
        rl[mf * 2 + 1] = get_label(labels_raw, row0 + m0 + mf * 16 + g + 8, is64);
    }

    // per-lane ldmatrix address components
    const uint32_t aRowOff = (uint32_t)(m0 + (lane & 15)) * 256u;
    const int kh = lane >> 4;                                   // A k-half bit
    const uint32_t bRowOff = (uint32_t)(n0 + (lane & 7) + ((lane >> 4) & 1) * 8) * 256u;
    const int kb = (lane >> 3) & 1;                             // B k-half bit
    const int sx = lane & 7;                                    // swizzle xor

    // prologue: A (resident) + B0 as group0; B1 as group1
    stage_tile(Abase, row0, tid);
    stage_tile(Bbuf0, split * COLS_PER_SPLIT + 0 * BN, tid);
    CP_COMMIT();
    stage_tile(Bbuf1, split * COLS_PER_SPLIT + 1 * BN, tid);
    CP_COMMIT();

    float tot[8], pos[8];
    #pragma unroll
    for (int i = 0; i < 8; i++) { tot[i] = 0.f; pos[i] = 0.f; }

    for (int t = 0; t < NTILES; ++t) {
        const int col0 = split * COLS_PER_SPLIT + t * BN;
        const uint32_t Bb = (t & 1) ? Bbuf1 : Bbuf0;
        const int cb = t & 1;

        CP_WAIT1();                              // B(t) resident (this thread)
        int cl_tmp = 0;
        if (tid < BN) cl_tmp = get_label(labels_raw, col0 + tid, is64);
        if (tid < BN) s_cl[cb][tid] = cl_tmp;
        __syncthreads();                         // B(t)+labels visible; prev epilogue done

        float acc[64];
        #pragma unroll
        for (int i = 0; i < 64; i++) acc[i] = 0.f;

        // ---- pass 1+2: Ahi*(Bhi) and Ahi*(Blo) ----
        #pragma unroll
        for (int ks = 0; ks < 8; ks++) {
            uint32_t a0[4], a1[4], a2[4], a3[4];
            uint32_t ac = (uint32_t)(((2 * ks + kh) ^ sx) << 4);
            {
                uint32_t aA = Abase + aRowOff + ac;   // hi plane
                ldsm4(a0[0], a1[0], a2[0], a3[0], aA);
                ldsm4(a0[1], a1[1], a2[1], a3[1], aA + 4096u);
                ldsm4(a0[2], a1[2], a2[2], a3[2], aA + 8192u);
                ldsm4(a0[3], a1[3], a2[3], a3[3], aA + 12288u);
            }
            uint32_t bc = (uint32_t)(((2 * ks + kb) ^ sx) << 4);
            {
                uint32_t b[8];
                uint32_t bA = Bb + bRowOff + bc;      // hi plane
                ldsm4(b[0], b[1], b[2], b[3], bA);
                ldsm4(b[4], b[5], b[6], b[7], bA + 4096u);
                #pragma unroll
                for (int mf = 0; mf < 4; mf++)
                    #pragma unroll
                    for (int nf = 0; nf < 4; nf++) {
                        int d = (mf * 4 + nf) * 4;
                        mma16816(acc[d], acc[d+1], acc[d+2], acc[d+3],
                                 a0[mf], a1[mf], a2[mf], a3[mf],
                                 b[nf * 2], b[nf * 2 + 1]);
                    }
            }
            {
                uint32_t b[8];
                uint32_t bA = Bb + PLANE + bRowOff + bc;  // lo plane
                ldsm4(b[0], b[1], b[2], b[3], bA);
                ldsm4(b[4], b[5], b[6], b[7], bA + 4096u);
                #pragma unroll
                for (int mf = 0; mf < 4; mf++)
                    #pragma unroll
                    for (int nf = 0; nf < 4; nf++) {
                        int d = (mf * 4 + nf) * 4;
                        mma16816(acc[d], acc[d+1], acc[d+2], acc[d+3],
                                 a0[mf], a1[mf], a2[mf], a3[mf],
                                 b[nf * 2], b[nf * 2 + 1]);
                    }
            }
        }
        // ---- pass 3: Alo*(Bhi) ----
        #pragma unroll
        for (int ks = 0; ks < 8; ks++) {
            uint32_t a0[4], a1[4], a2[4], a3[4];
            uint32_t ac = (uint32_t)(((2 * ks + kh) ^ sx) << 4);
            uint32_t aA = Abase + PLANE + aRowOff + ac;   // lo plane
            ldsm4(a0[0], a1[0], a2[0], a3[0], aA);
            ldsm4(a0[1], a1[1], a2[1], a3[1], aA + 4096u);
            ldsm4(a0[2], a1[2], a2[2], a3[2], aA + 8192u);
            ldsm4(a0[3], a1[3], a2[3], a3[3], aA + 12288u);

            uint32_t b[8];
            uint32_t bc = (uint32_t)(((2 * ks + kb) ^ sx) << 4);
            uint32_t bA = Bb + bRowOff + bc;              // hi plane
            ldsm4(b[0], b[1], b[2], b[3], bA);
            ldsm4(b[4], b[5], b[6], b[7], bA + 4096u);
            #pragma unroll
            for (int mf = 0; mf < 4; mf++)
                #pragma unroll
                for (int nf = 0; nf < 4; nf++) {
                    int d = (mf * 4 + nf) * 4;
                    mma16816(acc[d], acc[d+1], acc[d+2], acc[d+3],
                             a0[mf], a1[mf], a2[mf], a3[mf],
                             b[nf * 2], b[nf * 2 + 1]);
                }
        }

        __syncthreads();                         // all warps done reading Bb
        if (t + 2 < NTILES)
            stage_tile(Bb, split * COLS_PER_SPLIT + (t + 2) * BN, tid);
        CP_COMMIT();                             // commit (possibly empty) group

        // ---- epilogue: exp2 + masks + row-sum accumulation ----
        const int diag = (col0 == row0);
        #pragma unroll
        for (int nf = 0; nf < 4; nf++) {
            const int lc0 = n0 + nf * 8 + tig * 2;
            const int cl0 = s_cl[cb][lc0];
            const int cl1 = s_cl[cb][lc0 + 1];
            #pragma unroll
            for (int mf = 0; mf < 4; mf++) {
                const int d = (mf * 4 + nf) * 4;
                float e00 = ex2f(acc[d]);
                float e01 = ex2f(acc[d + 1]);
                float e10 = ex2f(acc[d + 2]);
                float e11 = ex2f(acc[d + 3]);
                if (diag) {
                    const int lr0 = m0 + mf * 16 + g;
                    const int lr1 = lr0 + 8;
                    if (lr0 == lc0)     e00 = 0.f;
                    if (lr0 == lc0 + 1) e01 = 0.f;
                    if (lr1 == lc0)     e10 = 0.f;
                    if (lr1 == lc0 + 1) e11 = 0.f;
                }
                tot[mf * 2]     += e00 + e01;
                tot[mf * 2 + 1] += e10 + e11;
                pos[mf * 2]     += (cl0 == rl[mf * 2] ? e00 : 0.f)
                                 + (cl1 == rl[mf * 2] ? e01 : 0.f);
                pos[mf * 2 + 1] += (cl0 == rl[mf * 2 + 1] ? e10 : 0.f)
                                 + (cl1 == rl[mf * 2 + 1] ? e11 : 0.f);
            }
        }
    }

    // reduce over the 4 threads-in-group (same rows, different columns)
    #pragma unroll
    for (int i = 0; i < 8; i++) {
        tot[i] += __shfl_xor_sync(0xFFFFFFFFu, tot[i], 1);
        tot[i] += __shfl_xor_sync(0xFFFFFFFFu, tot[i], 2);
        pos[i] += __shfl_xor_sync(0xFFFFFFFFu, pos[i], 1);
        pos[i] += __shfl_xor_sync(0xFFFFFFFFu, pos[i], 2);
    }
    if (tig == 0) {
        #pragma unroll
        for (int mf = 0; mf < 4; mf++) {
            s_red[0][m0 + mf * 16 + g][wn]     = tot[mf * 2];
            s_red[0][m0 + mf * 16 + g + 8][wn] = tot[mf * 2 + 1];
            s_red[1][m0 + mf * 16 + g][wn]     = pos[mf * 2];
            s_red[1][m0 + mf * 16 + g + 8][wn] = pos[mf * 2 + 1];
        }
    }
    __syncthreads();
    if (tid < BM) {
        float T = s_red[0][tid][0] + s_red[0][tid][1] + s_red[0][tid][2] + s_red[0][tid][3];
        float P = s_red[1][tid][0] + s_red[1][tid][1] + s_red[1][tid][2] + s_red[1][tid][3];
        g_tot[split][row0 + tid] = T;
        g_pos[split][row0 + tid] = P;
    }
}

// ---------------------------------------------------------------------------
// finalize
// ---------------------------------------------------------------------------
__global__ void __launch_bounds__(256)
finalize1_kernel()
{
    __shared__ float ws[8], wc[8];
    const int tid = threadIdx.x;
    const int i = blockIdx.x * 256 + tid;
    float p = g_pos[0][i] + g_pos[1][i];
    float tt = g_tot[0][i] + g_tot[1][i];
    float loss = 0.f, c = 0.f;
    if (p > 0.f) {
        loss = -logf(p / (tt + 1e-8f) + 1e-8f);
        c = 1.f;
    }
    #pragma unroll
    for (int o = 16; o > 0; o >>= 1) {
        loss += __shfl_xor_sync(0xFFFFFFFFu, loss, o);
        c    += __shfl_xor_sync(0xFFFFFFFFu, c, o);
    }
    if ((tid & 31) == 0) { ws[tid >> 5] = loss; wc[tid >> 5] = c; }
    __syncthreads();
    if (tid == 0) {
        float S = 0.f, C = 0.f;
        #pragma unroll
        for (int w = 0; w < 8; w++) { S += ws[w]; C += wc[w]; }
        g_part[0][blockIdx.x] = S;
        g_part[1][blockIdx.x] = C;
    }
}

__global__ void __launch_bounds__(32)
finalize2_kernel(float* __restrict__ out)
{
    const int tid = threadIdx.x;
    float S = g_part[0][tid];
    float C = g_part[1][tid];
    #pragma unroll
    for (int o = 16; o > 0; o >>= 1) {
        S += __shfl_xor_sync(0xFFFFFFFFu, S, o);
        C += __shfl_xor_sync(0xFFFFFFFFu, C, o);
    }
    if (tid == 0) out[0] = (C > 0.f) ? S / fmaxf(C, 1.f) : 0.f;
}

// ---------------------------------------------------------------------------
extern "C" void kernel_launch(void* const* d_in, const int* in_sizes, int n_in,
                              void* d_out, int out_size)
{
    const float* emb = (const float*)d_in[0];
    const void* labels = d_in[1];
    float* out = (float*)d_out;

    const int dyn_smem = 1024 + 6 * PLANE;   // pad + A(2 planes) + 2x B(2 planes)
    cudaFuncSetAttribute(contrastive_mma_kernel,
                         cudaFuncAttributeMaxDynamicSharedMemorySize, dyn_smem);

    convert_kernel<<<512, 256>>>(emb);
    dim3 grid(N_ROWS / BM, NSPLIT);
    contrastive_mma_kernel<<<grid, THREADS, dyn_smem>>>(labels);
    finalize1_kernel<<<32, 256>>>();
    finalize2_kernel<<<1, 32>>>(out);
}

// round 5
// speedup vs baseline: 5.1543x; 1.6194x over previous
#include <cuda_runtime.h>
#include <cuda_fp16.h>
#include <cstdint>

// ============================================================================
// ContrastiveLoss via mma.sync fp16 hi/lo-split GEMM, UPPER-TRIANGLE ONLY.
// exp(E·E^T) is symmetric: tile (i,j) provides row sums for block i AND
// (via its column sums) row sums for block j. 2080 tiles instead of 4096.
// Deterministic: every (tile -> slot) write is unique, overwrite semantics,
// fixed-order reduction kernel.
// R5 fix: B double-buffer parity is LOCAL to the chunk ((t - f0) & 1); the
// global-parity indexing in R4 swapped buffers for chunks with odd f0.
// ============================================================================

#define N_ROWS 8192
#define DIM    128
#define BM     128
#define BN     128
#define NBLK   64            // 8192/128 row blocks
#define TOTTILES 2080        // NBLK*(NBLK+1)/2
#define NCTA   148
#define THREADS 256
#define PLANE  32768         // one 128x128 fp16 plane in smem

// sqrt(log2(e)/0.07): folded into BOTH operands so acc == (log2e/T) * dot
#define SQRT_SCALE 4.53981642f

// ---------------------------------------------------------------------------
// device scratch
// ---------------------------------------------------------------------------
__device__ float g_rpart[NBLK][2][N_ROWS];   // tile (i,j) row sums  -> [j][a][i*128+r]
__device__ float g_cpart[NBLK][2][N_ROWS];   // tile (i,j) col sums  -> [i][a][j*128+c]
__device__ float g_part[2][32];
__device__ __align__(16) __half g_hi[N_ROWS * DIM];
__device__ __align__(16) __half g_lo[N_ROWS * DIM];

// ---------------------------------------------------------------------------
// helpers
// ---------------------------------------------------------------------------
__device__ __forceinline__ uint32_t smem_u32(const void* p) {
    uint32_t a;
    asm("{ .reg .u64 t; cvta.to.shared.u64 t, %1; cvt.u32.u64 %0, t; }"
        : "=r"(a) : "l"(p));
    return a;
}

__device__ __forceinline__ float ex2f(float x) {
    float y;
    asm("ex2.approx.ftz.f32 %0, %1;" : "=f"(y) : "f"(x));
    return y;
}

__device__ __forceinline__ void cp16(uint32_t dst, const void* src) {
    asm volatile("cp.async.cg.shared.global [%0], [%1], 16;"
                 :: "r"(dst), "l"(src) : "memory");
}
#define CP_COMMIT() asm volatile("cp.async.commit_group;" ::: "memory")
#define CP_WAIT0()  asm volatile("cp.async.wait_group 0;" ::: "memory")
#define CP_WAIT1()  asm volatile("cp.async.wait_group 1;" ::: "memory")

__device__ __forceinline__ void ldsm4(uint32_t& r0, uint32_t& r1,
                                      uint32_t& r2, uint32_t& r3, uint32_t a) {
    asm volatile("ldmatrix.sync.aligned.m8n8.x4.shared.b16 {%0,%1,%2,%3}, [%4];"
                 : "=r"(r0), "=r"(r1), "=r"(r2), "=r"(r3) : "r"(a));
}

__device__ __forceinline__ void mma16816(float& d0, float& d1, float& d2, float& d3,
                                         uint32_t a0, uint32_t a1, uint32_t a2, uint32_t a3,
                                         uint32_t b0, uint32_t b1) {
    asm volatile(
        "mma.sync.aligned.m16n8k16.row.col.f32.f16.f16.f32 "
        "{%0,%1,%2,%3}, {%4,%5,%6,%7}, {%8,%9}, {%0,%1,%2,%3};"
        : "+f"(d0), "+f"(d1), "+f"(d2), "+f"(d3)
        : "r"(a0), "r"(a1), "r"(a2), "r"(a3), "r"(b0), "r"(b1));
}

__device__ __forceinline__ int get_label(const void* p, int i, int is64) {
    if (is64) return (int)(((const long long*)p)[i]);
    return ((const int*)p)[i];
}

// triangle flattening: strip i holds tiles (i, j=i..63)
__device__ __forceinline__ int strip_start(int i) { return i * 64 - (i * (i - 1)) / 2; }
__device__ __forceinline__ void decode_tile(int f, int& i, int& j) {
    int s = 0;
    while (s < 63 && strip_start(s + 1) <= f) s++;
    i = s;
    j = s + (f - strip_start(s));
}
__device__ __forceinline__ void step_tile(int& i, int& j) {
    j++;
    if (j == 64) { i++; j = i; }
}

// smem tile addressing: 128 rows x 256B; 16B chunk c16 swizzled by row&7
__device__ __forceinline__ uint32_t tile_addr(uint32_t base, int row, int c16) {
    return base + (uint32_t)row * 256u + (uint32_t)(((c16 ^ (row & 7)) << 4));
}

// ---------------------------------------------------------------------------
// convert: fp32 emb -> prescaled fp16 hi/lo planes, row-major
// ---------------------------------------------------------------------------
__global__ void __launch_bounds__(256)
convert_kernel(const float* __restrict__ emb)
{
    int f = blockIdx.x * 256 + threadIdx.x;   // 131072 chunks of 8 elements
    int r = f >> 4;
    int c8 = f & 15;
    const float4* src = (const float4*)(emb + (size_t)r * DIM + c8 * 8);
    float4 v0 = src[0], v1 = src[1];
    float a[8] = {v0.x, v0.y, v0.z, v0.w, v1.x, v1.y, v1.z, v1.w};

    uint32_t hi[4], lo[4];
    #pragma unroll
    for (int p = 0; p < 4; p++) {
        float x0 = a[2 * p] * SQRT_SCALE;
        float x1 = a[2 * p + 1] * SQRT_SCALE;
        __half h0 = __float2half_rn(x0);
        __half h1 = __float2half_rn(x1);
        __half l0 = __float2half_rn(x0 - __half2float(h0));
        __half l1 = __float2half_rn(x1 - __half2float(h1));
        hi[p] = (uint32_t)__half_as_ushort(h0) | ((uint32_t)__half_as_ushort(h1) << 16);
        lo[p] = (uint32_t)__half_as_ushort(l0) | ((uint32_t)__half_as_ushort(l1) << 16);
    }
    size_t off = (size_t)r * DIM + c8 * 8;
    *(uint4*)(g_hi + off) = make_uint4(hi[0], hi[1], hi[2], hi[3]);
    *(uint4*)(g_lo + off) = make_uint4(lo[0], lo[1], lo[2], lo[3]);
}

// ---------------------------------------------------------------------------
// main MMA kernel
// ---------------------------------------------------------------------------
extern __shared__ __align__(16) char smem_dyn_c[];

// copy one 128-row hi+lo tile pair (global rows grow0..+127) into smem image
__device__ __forceinline__ void stage_tile(uint32_t base, int grow0, int tid) {
    #pragma unroll
    for (int i = 0; i < 16; i++) {
        int f = tid + i * THREADS;          // 0..4095
        int plane = f >> 11;
        int idx = f & 2047;
        int row = idx >> 4;
        int c16 = idx & 15;
        const __half* gsrc = (plane ? g_lo : g_hi);
        uint32_t dst = tile_addr(base + plane * PLANE, row, c16);
        cp16(dst, gsrc + (size_t)(grow0 + row) * DIM + c16 * 8);
    }
}

__global__ void __launch_bounds__(THREADS, 1)
contrastive_mma_kernel(const void* __restrict__ labels_raw)
{
    __shared__ int s_cl[2][BN];
    __shared__ int s_flag;
    __shared__ float s_rr[2][BM][4];
    __shared__ float s_cr[2][BN][2];

    const int tid = threadIdx.x;
    const int lane = tid & 31;
    const int wid = tid >> 5;
    const int c = blockIdx.x;

    uint32_t sbase = (smem_u32(smem_dyn_c) + 1023u) & ~1023u;
    const uint32_t Abase = sbase;
    const uint32_t Bbuf0 = sbase + 2u * PLANE;
    const uint32_t Bbuf1 = sbase + 4u * PLANE;

    if (tid == 0) {
        const int* li = (const int*)labels_raw;
        int is64 = 1;
        for (int i = 0; i < 64; i++)
            if (li[2 * i + 1] != 0) { is64 = 0; break; }
        s_flag = is64;
    }
    __syncthreads();
    const int is64 = s_flag;

    const int wm = wid >> 2;       // 0..1
    const int wn = wid & 3;        // 0..3
    const int m0 = wm * 64;
    const int n0 = wn * 32;
    const int g = lane >> 2;
    const int tig = lane & 3;

    // per-lane ldmatrix address components
    const uint32_t aRowOff = (uint32_t)(m0 + (lane & 15)) * 256u;
    const int kh = lane >> 4;                                   // A k-half bit
    const uint32_t bRowOff = (uint32_t)(n0 + (lane & 7) + ((lane >> 4) & 1) * 8) * 256u;
    const int kb = (lane >> 3) & 1;                             // B k-half bit
    const int sx = lane & 7;                                    // swizzle xor

    // chunk of the flattened triangle
    const int f0 = (c * TOTTILES) / NCTA;
    const int f1 = ((c + 1) * TOTTILES) / NCTA;
    int ti, tj;
    decode_tile(f0, ti, tj);

    // row labels for current strip
    int rl[8];
    #pragma unroll
    for (int mf = 0; mf < 4; mf++) {
        rl[mf * 2]     = get_label(labels_raw, ti * BM + m0 + mf * 16 + g, is64);
        rl[mf * 2 + 1] = get_label(labels_raw, ti * BM + m0 + mf * 16 + g + 8, is64);
    }

    // prologue: A(strip) + B(f0) in group 0 -> buffer 0 (local parity 0);
    //           B(f0+1) in group 1 -> buffer 1 (local parity 1)
    stage_tile(Abase, ti * BM, tid);
    stage_tile(Bbuf0, tj * BN, tid);
    CP_COMMIT();
    {
        int i1 = ti, j1 = tj;
        step_tile(i1, j1);
        if (f0 + 1 < f1) stage_tile(Bbuf1, j1 * BN, tid);
        CP_COMMIT();
    }

    for (int t = f0; t < f1; ++t) {
        const int cb = (t - f0) & 1;          // LOCAL parity (R5 fix)
        const uint32_t Bb = cb ? Bbuf1 : Bbuf0;

        if (t > f0 && tj == ti) {
            // new strip starts at its diagonal tile: reload A + row labels
            __syncthreads();                  // everyone done with old A
            stage_tile(Abase, ti * BM, tid);
            #pragma unroll
            for (int mf = 0; mf < 4; mf++) {
                rl[mf * 2]     = get_label(labels_raw, ti * BM + m0 + mf * 16 + g, is64);
                rl[mf * 2 + 1] = get_label(labels_raw, ti * BM + m0 + mf * 16 + g + 8, is64);
            }
            CP_COMMIT();
            CP_WAIT0();                       // drain everything (A + pending B)
        } else {
            CP_WAIT1();                       // B(t) resident
        }

        int cl_tmp = 0;
        if (tid < BN) cl_tmp = get_label(labels_raw, tj * BN + tid, is64);
        if (tid < BN) s_cl[cb][tid] = cl_tmp;
        __syncthreads();                      // B(t) + labels visible to all

        float acc[64];
        #pragma unroll
        for (int i = 0; i < 64; i++) acc[i] = 0.f;

        // ---- pass 1+2: Ahi*(Bhi) and Ahi*(Blo) ----
        #pragma unroll
        for (int ks = 0; ks < 8; ks++) {
            uint32_t a0[4], a1[4], a2[4], a3[4];
            uint32_t ac = (uint32_t)(((2 * ks + kh) ^ sx) << 4);
            {
                uint32_t aA = Abase + aRowOff + ac;   // hi plane
                ldsm4(a0[0], a1[0], a2[0], a3[0], aA);
                ldsm4(a0[1], a1[1], a2[1], a3[1], aA + 4096u);
                ldsm4(a0[2], a1[2], a2[2], a3[2], aA + 8192u);
                ldsm4(a0[3], a1[3], a2[3], a3[3], aA + 12288u);
            }
            uint32_t bc = (uint32_t)(((2 * ks + kb) ^ sx) << 4);
            {
                uint32_t b[8];
                uint32_t bA = Bb + bRowOff + bc;      // hi plane
                ldsm4(b[0], b[1], b[2], b[3], bA);
                ldsm4(b[4], b[5], b[6], b[7], bA + 4096u);
                #pragma unroll
                for (int mf = 0; mf < 4; mf++)
                    #pragma unroll
                    for (int nf = 0; nf < 4; nf++) {
                        int d = (mf * 4 + nf) * 4;
                        mma16816(acc[d], acc[d+1], acc[d+2], acc[d+3],
                                 a0[mf], a1[mf], a2[mf], a3[mf],
                                 b[nf * 2], b[nf * 2 + 1]);
                    }
            }
            {
                uint32_t b[8];
                uint32_t bA = Bb + PLANE + bRowOff + bc;  // lo plane
                ldsm4(b[0], b[1], b[2], b[3], bA);
                ldsm4(b[4], b[5], b[6], b[7], bA + 4096u);
                #pragma unroll
                for (int mf = 0; mf < 4; mf++)
                    #pragma unroll
                    for (int nf = 0; nf < 4; nf++) {
                        int d = (mf * 4 + nf) * 4;
                        mma16816(acc[d], acc[d+1], acc[d+2], acc[d+3],
                                 a0[mf], a1[mf], a2[mf], a3[mf],
                                 b[nf * 2], b[nf * 2 + 1]);
                    }
            }
        }
        // ---- pass 3: Alo*(Bhi) ----
        #pragma unroll
        for (int ks = 0; ks < 8; ks++) {
            uint32_t a0[4], a1[4], a2[4], a3[4];
            uint32_t ac = (uint32_t)(((2 * ks + kh) ^ sx) << 4);
            uint32_t aA = Abase + PLANE + aRowOff + ac;   // lo plane
            ldsm4(a0[0], a1[0], a2[0], a3[0], aA);
            ldsm4(a0[1], a1[1], a2[1], a3[1], aA + 4096u);
            ldsm4(a0[2], a1[2], a2[2], a3[2], aA + 8192u);
            ldsm4(a0[3], a1[3], a2[3], a3[3], aA + 12288u);

            uint32_t b[8];
            uint32_t bc = (uint32_t)(((2 * ks + kb) ^ sx) << 4);
            uint32_t bA = Bb + bRowOff + bc;              // hi plane
            ldsm4(b[0], b[1], b[2], b[3], bA);
            ldsm4(b[4], b[5], b[6], b[7], bA + 4096u);
            #pragma unroll
            for (int mf = 0; mf < 4; mf++)
                #pragma unroll
                for (int nf = 0; nf < 4; nf++) {
                    int d = (mf * 4 + nf) * 4;
                    mma16816(acc[d], acc[d+1], acc[d+2], acc[d+3],
                             a0[mf], a1[mf], a2[mf], a3[mf],
                             b[nf * 2], b[nf * 2 + 1]);
                }
        }

        __syncthreads();                      // all warps done reading Bb
        {                                     // prefetch B(t+2) into freed buffer
            int i2 = ti, j2 = tj;
            step_tile(i2, j2);
            step_tile(i2, j2);
            if (t + 2 < f1) stage_tile(Bb, j2 * BN, tid);
            CP_COMMIT();                      // commit (possibly empty) group
        }

        // ---- epilogue: exp2 + masks + per-tile row AND column sums ----
        float rt_[8], rp_[8], ct_[8], cp_[8];
        #pragma unroll
        for (int i = 0; i < 8; i++) { rt_[i] = 0.f; rp_[i] = 0.f; ct_[i] = 0.f; cp_[i] = 0.f; }
        const int diag = (ti == tj);
        #pragma unroll
        for (int nf = 0; nf < 4; nf++) {
            const int lc0 = n0 + nf * 8 + tig * 2;
            const int cl0 = s_cl[cb][lc0];
            const int cl1 = s_cl[cb][lc0 + 1];
            #pragma unroll
            for (int mf = 0; mf < 4; mf++) {
                const int d = (mf * 4 + nf) * 4;
                float e00 = ex2f(acc[d]);
                float e01 = ex2f(acc[d + 1]);
                float e10 = ex2f(acc[d + 2]);
                float e11 = ex2f(acc[d + 3]);
                if (diag) {
                    const int lr0 = m0 + mf * 16 + g;
                    const int lr1 = lr0 + 8;
                    if (lr0 == lc0)     e00 = 0.f;
                    if (lr0 == lc0 + 1) e01 = 0.f;
                    if (lr1 == lc0)     e10 = 0.f;
                    if (lr1 == lc0 + 1) e11 = 0.f;
                }
                float p00 = (cl0 == rl[mf * 2])     ? e00 : 0.f;
                float p01 = (cl1 == rl[mf * 2])     ? e01 : 0.f;
                float p10 = (cl0 == rl[mf * 2 + 1]) ? e10 : 0.f;
                float p11 = (cl1 == rl[mf * 2 + 1]) ? e11 : 0.f;
                rt_[mf * 2]     += e00 + e01;
                rt_[mf * 2 + 1] += e10 + e11;
                rp_[mf * 2]     += p00 + p01;
                rp_[mf * 2 + 1] += p10 + p11;
                ct_[nf * 2]     += e00 + e10;
                ct_[nf * 2 + 1] += e01 + e11;
                cp_[nf * 2]     += p00 + p10;
                cp_[nf * 2 + 1] += p01 + p11;
            }
        }
        // rows: reduce over tig (4 threads share rows)
        #pragma unroll
        for (int i = 0; i < 8; i++) {
            rt_[i] += __shfl_xor_sync(0xFFFFFFFFu, rt_[i], 1);
            rt_[i] += __shfl_xor_sync(0xFFFFFFFFu, rt_[i], 2);
            rp_[i] += __shfl_xor_sync(0xFFFFFFFFu, rp_[i], 1);
            rp_[i] += __shfl_xor_sync(0xFFFFFFFFu, rp_[i], 2);
        }
        // cols: reduce over g (8 threads share cols)
        #pragma unroll
        for (int i = 0; i < 8; i++) {
            ct_[i] += __shfl_xor_sync(0xFFFFFFFFu, ct_[i], 4);
            ct_[i] += __shfl_xor_sync(0xFFFFFFFFu, ct_[i], 8);
            ct_[i] += __shfl_xor_sync(0xFFFFFFFFu, ct_[i], 16);
            cp_[i] += __shfl_xor_sync(0xFFFFFFFFu, cp_[i], 4);
            cp_[i] += __shfl_xor_sync(0xFFFFFFFFu, cp_[i], 8);
            cp_[i] += __shfl_xor_sync(0xFFFFFFFFu, cp_[i], 16);
        }
        if (tig == 0) {
            #pragma unroll
            for (int mf = 0; mf < 4; mf++) {
                s_rr[0][m0 + mf * 16 + g][wn]     = rt_[mf * 2];
                s_rr[0][m0 + mf * 16 + g + 8][wn] = rt_[mf * 2 + 1];
                s_rr[1][m0 + mf * 16 + g][wn]     = rp_[mf * 2];
                s_rr[1][m0 + mf * 16 + g + 8][wn] = rp_[mf * 2 + 1];
            }
        }
        if (lane < 4) {   // lanes with g==0 (butterfly leaves result everywhere)
            #pragma unroll
            for (int nf = 0; nf < 4; nf++) {
                s_cr[0][n0 + nf * 8 + lane * 2][wm]     = ct_[nf * 2];
                s_cr[0][n0 + nf * 8 + lane * 2 + 1][wm] = ct_[nf * 2 + 1];
                s_cr[1][n0 + nf * 8 + lane * 2][wm]     = cp_[nf * 2];
                s_cr[1][n0 + nf * 8 + lane * 2 + 1][wm] = cp_[nf * 2 + 1];
            }
        }
        __syncthreads();
        if (tid < BM) {
            float T = s_rr[0][tid][0] + s_rr[0][tid][1] + s_rr[0][tid][2] + s_rr[0][tid][3];
            float P = s_rr[1][tid][0] + s_rr[1][tid][1] + s_rr[1][tid][2] + s_rr[1][tid][3];
            g_rpart[tj][0][ti * BM + tid] = T;
            g_rpart[tj][1][ti * BM + tid] = P;
            float CT = s_cr[0][tid][0] + s_cr[0][tid][1];
            float CP = s_cr[1][tid][0] + s_cr[1][tid][1];
            g_cpart[ti][0][tj * BN + tid] = CT;
            g_cpart[ti][1][tj * BN + tid] = CP;
        }

        step_tile(ti, tj);
    }
}

// ---------------------------------------------------------------------------
// reduce + finalize
// ---------------------------------------------------------------------------
__global__ void __launch_bounds__(256)
reduce1_kernel()
{
    __shared__ float ws[8], wc[8];
    const int tid = threadIdx.x;
    const int r = blockIdx.x * 256 + tid;
    const int b = r >> 7;

    float tt = 0.f, pp = 0.f;
    for (int j = b; j < NBLK; j++) {
        tt += g_rpart[j][0][r];
        pp += g_rpart[j][1][r];
    }
    for (int i = 0; i < b; i++) {
        tt += g_cpart[i][0][r];
        pp += g_cpart[i][1][r];
    }

    float loss = 0.f, cnt = 0.f;
    if (pp > 0.f) {
        loss = -logf(pp / (tt + 1e-8f) + 1e-8f);
        cnt = 1.f;
    }
    #pragma unroll
    for (int o = 16; o > 0; o >>= 1) {
        loss += __shfl_xor_sync(0xFFFFFFFFu, loss, o);
        cnt  += __shfl_xor_sync(0xFFFFFFFFu, cnt, o);
    }
    if ((tid & 31) == 0) { ws[tid >> 5] = loss; wc[tid >> 5] = cnt; }
    __syncthreads();
    if (tid == 0) {
        float S = 0.f, C = 0.f;
        #pragma unroll
        for (int w = 0; w < 8; w++) { S += ws[w]; C += wc[w]; }
        g_part[0][blockIdx.x] = S;
        g_part[1][blockIdx.x] = C;
    }
}

__global__ void __launch_bounds__(32)
reduce2_kernel(float* __restrict__ out)
{
    const int tid = threadIdx.x;
    float S = g_part[0][tid];
    float C = g_part[1][tid];
    #pragma unroll
    for (int o = 16; o > 0; o >>= 1) {
        S += __shfl_xor_sync(0xFFFFFFFFu, S, o);
        C += __shfl_xor_sync(0xFFFFFFFFu, C, o);
    }
    if (tid == 0) out[0] = (C > 0.f) ? S / fmaxf(C, 1.f) : 0.f;
}

// ---------------------------------------------------------------------------
extern "C" void kernel_launch(void* const* d_in, const int* in_sizes, int n_in,
                              void* d_out, int out_size)
{
    const float* emb = (const float*)d_in[0];
    const void* labels = d_in[1];
    float* out = (float*)d_out;

    const int dyn_smem = 1024 + 6 * PLANE;   // pad + A(2 planes) + 2x B(2 planes)
    cudaFuncSetAttribute(contrastive_mma_kernel,
                         cudaFuncAttributeMaxDynamicSharedMemorySize, dyn_smem);

    convert_kernel<<<512, 256>>>(emb);
    contrastive_mma_kernel<<<NCTA, THREADS, dyn_smem>>>(labels);
    reduce1_kernel<<<32, 256>>>();
    reduce2_kernel<<<1, 32>>>(out);
}

// round 6
// speedup vs baseline: 6.4219x; 1.2459x over previous
#include <cuda_runtime.h>
#include <cuda_fp16.h>
#include <cstdint>

// ============================================================================
// ContrastiveLoss via mma.sync fp16 hi/lo-split GEMM, UPPER-TRIANGLE ONLY.
// R6: 2-pass split (AhiBhi + AloBhi; AhiBlo dropped, ~3e-4 per-element exp
// error, averages out in the row sums). B needs only its hi plane -> half
// the B staging traffic and smem.
// exp(E·E^T) is symmetric: tile (i,j) provides row sums for block i AND
// (via its column sums) row sums for block j. 2080 tiles instead of 4096.
// Deterministic: every (tile -> slot) write is unique, overwrite semantics,
// fixed-order reduction kernel.
// ============================================================================

#define N_ROWS 8192
#define DIM    128
#define BM     128
#define BN     128
#define NBLK   64            // 8192/128 row blocks
#define TOTTILES 2080        // NBLK*(NBLK+1)/2
#define NCTA   148
#define THREADS 256
#define PLANE  32768         // one 128x128 fp16 plane in smem

// sqrt(log2(e)/0.07): folded into BOTH operands so acc == (log2e/T) * dot
#define SQRT_SCALE 4.53981642f

// ---------------------------------------------------------------------------
// device scratch
// ---------------------------------------------------------------------------
__device__ float g_rpart[NBLK][2][N_ROWS];   // tile (i,j) row sums  -> [j][a][i*128+r]
__device__ float g_cpart[NBLK][2][N_ROWS];   // tile (i,j) col sums  -> [i][a][j*128+c]
__device__ float g_part[2][32];
__device__ __align__(16) __half g_hi[N_ROWS * DIM];
__device__ __align__(16) __half g_lo[N_ROWS * DIM];

// ---------------------------------------------------------------------------
// helpers
// ---------------------------------------------------------------------------
__device__ __forceinline__ uint32_t smem_u32(const void* p) {
    uint32_t a;
    asm("{ .reg .u64 t; cvta.to.shared.u64 t, %1; cvt.u32.u64 %0, t; }"
        : "=r"(a) : "l"(p));
    return a;
}

__device__ __forceinline__ float ex2f(float x) {
    float y;
    asm("ex2.approx.ftz.f32 %0, %1;" : "=f"(y) : "f"(x));
    return y;
}

__device__ __forceinline__ void cp16(uint32_t dst, const void* src) {
    asm volatile("cp.async.cg.shared.global [%0], [%1], 16;"
                 :: "r"(dst), "l"(src) : "memory");
}
#define CP_COMMIT() asm volatile("cp.async.commit_group;" ::: "memory")
#define CP_WAIT0()  asm volatile("cp.async.wait_group 0;" ::: "memory")
#define CP_WAIT1()  asm volatile("cp.async.wait_group 1;" ::: "memory")

__device__ __forceinline__ void ldsm4(uint32_t& r0, uint32_t& r1,
                                      uint32_t& r2, uint32_t& r3, uint32_t a) {
    asm volatile("ldmatrix.sync.aligned.m8n8.x4.shared.b16 {%0,%1,%2,%3}, [%4];"
                 : "=r"(r0), "=r"(r1), "=r"(r2), "=r"(r3) : "r"(a));
}

__device__ __forceinline__ void mma16816(float& d0, float& d1, float& d2, float& d3,
                                         uint32_t a0, uint32_t a1, uint32_t a2, uint32_t a3,
                                         uint32_t b0, uint32_t b1) {
    asm volatile(
        "mma.sync.aligned.m16n8k16.row.col.f32.f16.f16.f32 "
        "{%0,%1,%2,%3}, {%4,%5,%6,%7}, {%8,%9}, {%0,%1,%2,%3};"
        : "+f"(d0), "+f"(d1), "+f"(d2), "+f"(d3)
        : "r"(a0), "r"(a1), "r"(a2), "r"(a3), "r"(b0), "r"(b1));
}

__device__ __forceinline__ int get_label(const void* p, int i, int is64) {
    if (is64) return (int)(((const long long*)p)[i]);
    return ((const int*)p)[i];
}

// triangle flattening: strip i holds tiles (i, j=i..63)
__device__ __forceinline__ int strip_start(int i) { return i * 64 - (i * (i - 1)) / 2; }
__device__ __forceinline__ void decode_tile(int f, int& i, int& j) {
    int s = 0;
    while (s < 63 && strip_start(s + 1) <= f) s++;
    i = s;
    j = s + (f - strip_start(s));
}
__device__ __forceinline__ void step_tile(int& i, int& j) {
    j++;
    if (j == 64) { i++; j = i; }
}

// smem tile addressing: 128 rows x 256B; 16B chunk c16 swizzled by row&7
__device__ __forceinline__ uint32_t tile_addr(uint32_t base, int row, int c16) {
    return base + (uint32_t)row * 256u + (uint32_t)(((c16 ^ (row & 7)) << 4));
}

// ---------------------------------------------------------------------------
// convert: fp32 emb -> prescaled fp16 hi/lo planes, row-major
// ---------------------------------------------------------------------------
__global__ void __launch_bounds__(256)
convert_kernel(const float* __restrict__ emb)
{
    int f = blockIdx.x * 256 + threadIdx.x;   // 131072 chunks of 8 elements
    int r = f >> 4;
    int c8 = f & 15;
    const float4* src = (const float4*)(emb + (size_t)r * DIM + c8 * 8);
    float4 v0 = src[0], v1 = src[1];
    float a[8] = {v0.x, v0.y, v0.z, v0.w, v1.x, v1.y, v1.z, v1.w};

    uint32_t hi[4], lo[4];
    #pragma unroll
    for (int p = 0; p < 4; p++) {
        float x0 = a[2 * p] * SQRT_SCALE;
        float x1 = a[2 * p + 1] * SQRT_SCALE;
        __half h0 = __float2half_rn(x0);
        __half h1 = __float2half_rn(x1);
        __half l0 = __float2half_rn(x0 - __half2float(h0));
        __half l1 = __float2half_rn(x1 - __half2float(h1));
        hi[p] = (uint32_t)__half_as_ushort(h0) | ((uint32_t)__half_as_ushort(h1) << 16);
        lo[p] = (uint32_t)__half_as_ushort(l0) | ((uint32_t)__half_as_ushort(l1) << 16);
    }
    size_t off = (size_t)r * DIM + c8 * 8;
    *(uint4*)(g_hi + off) = make_uint4(hi[0], hi[1], hi[2], hi[3]);
    *(uint4*)(g_lo + off) = make_uint4(lo[0], lo[1], lo[2], lo[3]);
}

// ---------------------------------------------------------------------------
// main MMA kernel
// ---------------------------------------------------------------------------
extern __shared__ __align__(16) char smem_dyn_c[];

// A: hi+lo planes (4096 16B chunks)
__device__ __forceinline__ void stage_tile_A(uint32_t base, int grow0, int tid) {
    #pragma unroll
    for (int i = 0; i < 16; i++) {
        int f = tid + i * THREADS;          // 0..4095
        int plane = f >> 11;
        int idx = f & 2047;
        int row = idx >> 4;
        int c16 = idx & 15;
        const __half* gsrc = (plane ? g_lo : g_hi);
        uint32_t dst = tile_addr(base + plane * PLANE, row, c16);
        cp16(dst, gsrc + (size_t)(grow0 + row) * DIM + c16 * 8);
    }
}

// B: hi plane only (2048 16B chunks)
__device__ __forceinline__ void stage_tile_B(uint32_t base, int grow0, int tid) {
    #pragma unroll
    for (int i = 0; i < 8; i++) {
        int f = tid + i * THREADS;          // 0..2047
        int row = f >> 4;
        int c16 = f & 15;
        uint32_t dst = tile_addr(base, row, c16);
        cp16(dst, g_hi + (size_t)(grow0 + row) * DIM + c16 * 8);
    }
}

__global__ void __launch_bounds__(THREADS, 1)
contrastive_mma_kernel(const void* __restrict__ labels_raw)
{
    __shared__ int s_cl[2][BN];
    __shared__ int s_flag;
    __shared__ float s_rr[2][BM][4];
    __shared__ float s_cr[2][BN][2];

    const int tid = threadIdx.x;
    const int lane = tid & 31;
    const int wid = tid >> 5;
    const int c = blockIdx.x;

    uint32_t sbase = (smem_u32(smem_dyn_c) + 1023u) & ~1023u;
    const uint32_t Abase = sbase;                  // 2 planes (hi, lo)
    const uint32_t Bbuf0 = sbase + 2u * PLANE;     // 1 plane (hi)
    const uint32_t Bbuf1 = sbase + 3u * PLANE;     // 1 plane (hi)

    if (tid == 0) {
        const int* li = (const int*)labels_raw;
        int is64 = 1;
        for (int i = 0; i < 64; i++)
            if (li[2 * i + 1] != 0) { is64 = 0; break; }
        s_flag = is64;
    }
    __syncthreads();
    const int is64 = s_flag;

    const int wm = wid >> 2;       // 0..1
    const int wn = wid & 3;        // 0..3
    const int m0 = wm * 64;
    const int n0 = wn * 32;
    const int g = lane >> 2;
    const int tig = lane & 3;

    // per-lane ldmatrix address components
    const uint32_t aRowOff = (uint32_t)(m0 + (lane & 15)) * 256u;
    const int kh = lane >> 4;                                   // A k-half bit
    const uint32_t bRowOff = (uint32_t)(n0 + (lane & 7) + ((lane >> 4) & 1) * 8) * 256u;
    const int kb = (lane >> 3) & 1;                             // B k-half bit
    const int sx = lane & 7;                                    // swizzle xor

    // chunk of the flattened triangle
    const int f0 = (c * TOTTILES) / NCTA;
    const int f1 = ((c + 1) * TOTTILES) / NCTA;
    int ti, tj;
    decode_tile(f0, ti, tj);

    // row labels for current strip
    int rl[8];
    #pragma unroll
    for (int mf = 0; mf < 4; mf++) {
        rl[mf * 2]     = get_label(labels_raw, ti * BM + m0 + mf * 16 + g, is64);
        rl[mf * 2 + 1] = get_label(labels_raw, ti * BM + m0 + mf * 16 + g + 8, is64);
    }

    // prologue: A(strip) + B(f0) in group 0 -> buffer 0 (local parity 0);
    //           B(f0+1) in group 1 -> buffer 1 (local parity 1)
    stage_tile_A(Abase, ti * BM, tid);
    stage_tile_B(Bbuf0, tj * BN, tid);
    CP_COMMIT();
    {
        int i1 = ti, j1 = tj;
        step_tile(i1, j1);
        if (f0 + 1 < f1) stage_tile_B(Bbuf1, j1 * BN, tid);
        CP_COMMIT();
    }

    for (int t = f0; t < f1; ++t) {
        const int cb = (t - f0) & 1;          // LOCAL parity
        const uint32_t Bb = cb ? Bbuf1 : Bbuf0;

        if (t > f0 && tj == ti) {
            // new strip starts at its diagonal tile: reload A + row labels
            __syncthreads();                  // everyone done with old A
            stage_tile_A(Abase, ti * BM, tid);
            #pragma unroll
            for (int mf = 0; mf < 4; mf++) {
                rl[mf * 2]     = get_label(labels_raw, ti * BM + m0 + mf * 16 + g, is64);
                rl[mf * 2 + 1] = get_label(labels_raw, ti * BM + m0 + mf * 16 + g + 8, is64);
            }
            CP_COMMIT();
            CP_WAIT0();                       // drain everything (A + pending B)
        } else {
            CP_WAIT1();                       // B(t) resident
        }

        int cl_tmp = 0;
        if (tid < BN) cl_tmp = get_label(labels_raw, tj * BN + tid, is64);
        if (tid < BN) s_cl[cb][tid] = cl_tmp;
        __syncthreads();                      // B(t) + labels visible to all

        float acc[64];
        #pragma unroll
        for (int i = 0; i < 64; i++) acc[i] = 0.f;

        // ---- pass 1: Ahi*Bhi ----
        #pragma unroll
        for (int ks = 0; ks < 8; ks++) {
            uint32_t a0[4], a1[4], a2[4], a3[4];
            uint32_t ac = (uint32_t)(((2 * ks + kh) ^ sx) << 4);
            uint32_t aA = Abase + aRowOff + ac;           // hi plane
            ldsm4(a0[0], a1[0], a2[0], a3[0], aA);
            ldsm4(a0[1], a1[1], a2[1], a3[1], aA + 4096u);
            ldsm4(a0[2], a1[2], a2[2], a3[2], aA + 8192u);
            ldsm4(a0[3], a1[3], a2[3], a3[3], aA + 12288u);

            uint32_t b[8];
            uint32_t bc = (uint32_t)(((2 * ks + kb) ^ sx) << 4);
            uint32_t bA = Bb + bRowOff + bc;              // hi plane
            ldsm4(b[0], b[1], b[2], b[3], bA);
            ldsm4(b[4], b[5], b[6], b[7], bA + 4096u);
            #pragma unroll
            for (int mf = 0; mf < 4; mf++)
                #pragma unroll
                for (int nf = 0; nf < 4; nf++) {
                    int d = (mf * 4 + nf) * 4;
                    mma16816(acc[d], acc[d+1], acc[d+2], acc[d+3],
                             a0[mf], a1[mf], a2[mf], a3[mf],
                             b[nf * 2], b[nf * 2 + 1]);
                }
        }
        // ---- pass 2: Alo*Bhi ----
        #pragma unroll
        for (int ks = 0; ks < 8; ks++) {
            uint32_t a0[4], a1[4], a2[4], a3[4];
            uint32_t ac = (uint32_t)(((2 * ks + kh) ^ sx) << 4);
            uint32_t aA = Abase + PLANE + aRowOff + ac;   // lo plane
            ldsm4(a0[0], a1[0], a2[0], a3[0], aA);
            ldsm4(a0[1], a1[1], a2[1], a3[1], aA + 4096u);
            ldsm4(a0[2], a1[2], a2[2], a3[2], aA + 8192u);
            ldsm4(a0[3], a1[3], a2[3], a3[3], aA + 12288u);

            uint32_t b[8];
            uint32_t bc = (uint32_t)(((2 * ks + kb) ^ sx) << 4);
            uint32_t bA = Bb + bRowOff + bc;              // hi plane
            ldsm4(b[0], b[1], b[2], b[3], bA);
            ldsm4(b[4], b[5], b[6], b[7], bA + 4096u);
            #pragma unroll
            for (int mf = 0; mf < 4; mf++)
                #pragma unroll
                for (int nf = 0; nf < 4; nf++) {
                    int d = (mf * 4 + nf) * 4;
                    mma16816(acc[d], acc[d+1], acc[d+2], acc[d+3],
                             a0[mf], a1[mf], a2[mf], a3[mf],
                             b[nf * 2], b[nf * 2 + 1]);
                }
        }

        __syncthreads();                      // all warps done reading Bb
        {                                     // prefetch B(t+2) into freed buffer
            int i2 = ti, j2 = tj;
            step_tile(i2, j2);
            step_tile(i2, j2);
            if (t + 2 < f1) stage_tile_B(Bb, j2 * BN, tid);
            CP_COMMIT();                      // commit (possibly empty) group
        }

        // ---- epilogue: exp2 + masks + per-tile row AND column sums ----
        float rt_[8], rp_[8], ct_[8], cp_[8];
        #pragma unroll
        for (int i = 0; i < 8; i++) { rt_[i] = 0.f; rp_[i] = 0.f; ct_[i] = 0.f; cp_[i] = 0.f; }
        const int diag = (ti == tj);
        #pragma unroll
        for (int nf = 0; nf < 4; nf++) {
            const int lc0 = n0 + nf * 8 + tig * 2;
            const int cl0 = s_cl[cb][lc0];
            const int cl1 = s_cl[cb][lc0 + 1];
            #pragma unroll
            for (int mf = 0; mf < 4; mf++) {
                const int d = (mf * 4 + nf) * 4;
                float e00 = ex2f(acc[d]);
                float e01 = ex2f(acc[d + 1]);
                float e10 = ex2f(acc[d + 2]);
                float e11 = ex2f(acc[d + 3]);
                if (diag) {
                    const int lr0 = m0 + mf * 16 + g;
                    const int lr1 = lr0 + 8;
                    if (lr0 == lc0)     e00 = 0.f;
                    if (lr0 == lc0 + 1) e01 = 0.f;
                    if (lr1 == lc0)     e10 = 0.f;
                    if (lr1 == lc0 + 1) e11 = 0.f;
                }
                float p00 = (cl0 == rl[mf * 2])     ? e00 : 0.f;
                float p01 = (cl1 == rl[mf * 2])     ? e01 : 0.f;
                float p10 = (cl0 == rl[mf * 2 + 1]) ? e10 : 0.f;
                float p11 = (cl1 == rl[mf * 2 + 1]) ? e11 : 0.f;
                rt_[mf * 2]     += e00 + e01;
                rt_[mf * 2 + 1] += e10 + e11;
                rp_[mf * 2]     += p00 + p01;
                rp_[mf * 2 + 1] += p10 + p11;
                ct_[nf * 2]     += e00 + e10;
                ct_[nf * 2 + 1] += e01 + e11;
                cp_[nf * 2]     += p00 + p10;
                cp_[nf * 2 + 1] += p01 + p11;
            }
        }
        // rows: reduce over tig (4 threads share rows)
        #pragma unroll
        for (int i = 0; i < 8; i++) {
            rt_[i] += __shfl_xor_sync(0xFFFFFFFFu, rt_[i], 1);
            rt_[i] += __shfl_xor_sync(0xFFFFFFFFu, rt_[i], 2);
            rp_[i] += __shfl_xor_sync(0xFFFFFFFFu, rp_[i], 1);
            rp_[i] += __shfl_xor_sync(0xFFFFFFFFu, rp_[i], 2);
        }
        // cols: reduce over g (8 threads share cols)
        #pragma unroll
        for (int i = 0; i < 8; i++) {
            ct_[i] += __shfl_xor_sync(0xFFFFFFFFu, ct_[i], 4);
            ct_[i] += __shfl_xor_sync(0xFFFFFFFFu, ct_[i], 8);
            ct_[i] += __shfl_xor_sync(0xFFFFFFFFu, ct_[i], 16);
            cp_[i] += __shfl_xor_sync(0xFFFFFFFFu, cp_[i], 4);
            cp_[i] += __shfl_xor_sync(0xFFFFFFFFu, cp_[i], 8);
            cp_[i] += __shfl_xor_sync(0xFFFFFFFFu, cp_[i], 16);
        }
        if (tig == 0) {
            #pragma unroll
            for (int mf = 0; mf < 4; mf++) {
                s_rr[0][m0 + mf * 16 + g][wn]     = rt_[mf * 2];
                s_rr[0][m0 + mf * 16 + g + 8][wn] = rt_[mf * 2 + 1];
                s_rr[1][m0 + mf * 16 + g][wn]     = rp_[mf * 2];
                s_rr[1][m0 + mf * 16 + g + 8][wn] = rp_[mf * 2 + 1];
            }
        }
        if (lane < 4) {   // lanes with g==0 (butterfly leaves result everywhere)
            #pragma unroll
            for (int nf = 0; nf < 4; nf++) {
                s_cr[0][n0 + nf * 8 + lane * 2][wm]     = ct_[nf * 2];
                s_cr[0][n0 + nf * 8 + lane * 2 + 1][wm] = ct_[nf * 2 + 1];
                s_cr[1][n0 + nf * 8 + lane * 2][wm]     = cp_[nf * 2];
                s_cr[1][n0 + nf * 8 + lane * 2 + 1][wm] = cp_[nf * 2 + 1];
            }
        }
        __syncthreads();
        if (tid < BM) {
            float T = s_rr[0][tid][0] + s_rr[0][tid][1] + s_rr[0][tid][2] + s_rr[0][tid][3];
            float P = s_rr[1][tid][0] + s_rr[1][tid][1] + s_rr[1][tid][2] + s_rr[1][tid][3];
            g_rpart[tj][0][ti * BM + tid] = T;
            g_rpart[tj][1][ti * BM + tid] = P;
            float CT = s_cr[0][tid][0] + s_cr[0][tid][1];
            float CP = s_cr[1][tid][0] + s_cr[1][tid][1];
            g_cpart[ti][0][tj * BN + tid] = CT;
            g_cpart[ti][1][tj * BN + tid] = CP;
        }

        step_tile(ti, tj);
    }
}

// ---------------------------------------------------------------------------
// reduce + finalize
// ---------------------------------------------------------------------------
__global__ void __launch_bounds__(256)
reduce1_kernel()
{
    __shared__ float ws[8], wc[8];
    const int tid = threadIdx.x;
    const int r = blockIdx.x * 256 + tid;
    const int b = r >> 7;

    float tt = 0.f, pp = 0.f;
    for (int j = b; j < NBLK; j++) {
        tt += g_rpart[j][0][r];
        pp += g_rpart[j][1][r];
    }
    for (int i = 0; i < b; i++) {
        tt += g_cpart[i][0][r];
        pp += g_cpart[i][1][r];
    }

    float loss = 0.f, cnt = 0.f;
    if (pp > 0.f) {
        loss = -logf(pp / (tt + 1e-8f) + 1e-8f);
        cnt = 1.f;
    }
    #pragma unroll
    for (int o = 16; o > 0; o >>= 1) {
        loss += __shfl_xor_sync(0xFFFFFFFFu, loss, o);
        cnt  += __shfl_xor_sync(0xFFFFFFFFu, cnt, o);
    }
    if ((tid & 31) == 0) { ws[tid >> 5] = loss; wc[tid >> 5] = cnt; }
    __syncthreads();
    if (tid == 0) {
        float S = 0.f, C = 0.f;
        #pragma unroll
        for (int w = 0; w < 8; w++) { S += ws[w]; C += wc[w]; }
        g_part[0][blockIdx.x] = S;
        g_part[1][blockIdx.x] = C;
    }
}

__global__ void __launch_bounds__(32)
reduce2_kernel(float* __restrict__ out)
{
    const int tid = threadIdx.x;
    float S = g_part[0][tid];
    float C = g_part[1][tid];
    #pragma unroll
    for (int o = 16; o > 0; o >>= 1) {
        S += __shfl_xor_sync(0xFFFFFFFFu, S, o);
        C += __shfl_xor_sync(0xFFFFFFFFu, C, o);
    }
    if (tid == 0) out[0] = (C > 0.f) ? S / fmaxf(C, 1.f) : 0.f;
}

// ---------------------------------------------------------------------------
extern "C" void kernel_launch(void* const* d_in, const int* in_sizes, int n_in,
                              void* d_out, int out_size)
{
    const float* emb = (const float*)d_in[0];
    const void* labels = d_in[1];
    float* out = (float*)d_out;

    const int dyn_smem = 1024 + 4 * PLANE;   // pad + A(hi,lo) + 2x B(hi)
    cudaFuncSetAttribute(contrastive_mma_kernel,
                         cudaFuncAttributeMaxDynamicSharedMemorySize, dyn_smem);

    convert_kernel<<<512, 256>>>(emb);
    contrastive_mma_kernel<<<NCTA, THREADS, dyn_smem>>>(labels);
    reduce1_kernel<<<32, 256>>>();
    reduce2_kernel<<<1, 32>>>(out);
}

// round 7
// speedup vs baseline: 7.1906x; 1.1197x over previous
#include <cuda_runtime.h>
#include <cuda_fp16.h>
#include <cstdint>

// ============================================================================
// ContrastiveLoss, single-pass fp16 mma.sync GEMM, upper triangle only.
// R7: 512 threads / 16 warps (warp tile 32x32, 16 acc regs), two n16-chunks
// per warp-tile each doing full-K MMA then immediate epilogue -> cross-warp
// MUFU/HMMA overlap. Single fp16 pass (measured R6 error margin ~3000x lets
// us drop the lo-plane correction entirely).
// Deterministic: per-tile slot writes unique, fixed-order reduction.
// ============================================================================

#define N_ROWS 8192
#define DIM    128
#define BM     128
#define BN     128
#define NBLK   64
#define TOTTILES 2080        // NBLK*(NBLK+1)/2
#define NCTA   148
#define THREADS 512
#define PLANE  32768         // one 128x128 fp16 plane

// sqrt(log2(e)/0.07): folded into BOTH operands so acc == (log2e/T) * dot
#define SQRT_SCALE 4.53981642f

// ---------------------------------------------------------------------------
__device__ float2 g_rpart[NBLK][N_ROWS];   // tile (i,j): rows -> [j][i*128+r]
__device__ float2 g_cpart[NBLK][N_ROWS];   // tile (i,j): cols -> [i][j*128+c]
__device__ float g_part[2][32];
__device__ __align__(16) __half g_hi[N_ROWS * DIM];

// ---------------------------------------------------------------------------
__device__ __forceinline__ uint32_t smem_u32(const void* p) {
    uint32_t a;
    asm("{ .reg .u64 t; cvta.to.shared.u64 t, %1; cvt.u32.u64 %0, t; }"
        : "=r"(a) : "l"(p));
    return a;
}

__device__ __forceinline__ float ex2f(float x) {
    float y;
    asm("ex2.approx.ftz.f32 %0, %1;" : "=f"(y) : "f"(x));
    return y;
}

__device__ __forceinline__ void cp16(uint32_t dst, const void* src) {
    asm volatile("cp.async.cg.shared.global [%0], [%1], 16;"
                 :: "r"(dst), "l"(src) : "memory");
}
#define CP_COMMIT() asm volatile("cp.async.commit_group;" ::: "memory")
#define CP_WAIT0()  asm volatile("cp.async.wait_group 0;" ::: "memory")
#define CP_WAIT1()  asm volatile("cp.async.wait_group 1;" ::: "memory")

__device__ __forceinline__ void ldsm4(uint32_t& r0, uint32_t& r1,
                                      uint32_t& r2, uint32_t& r3, uint32_t a) {
    asm volatile("ldmatrix.sync.aligned.m8n8.x4.shared.b16 {%0,%1,%2,%3}, [%4];"
                 : "=r"(r0), "=r"(r1), "=r"(r2), "=r"(r3) : "r"(a));
}

__device__ __forceinline__ void mma16816(float& d0, float& d1, float& d2, float& d3,
                                         uint32_t a0, uint32_t a1, uint32_t a2, uint32_t a3,
                                         uint32_t b0, uint32_t b1) {
    asm volatile(
        "mma.sync.aligned.m16n8k16.row.col.f32.f16.f16.f32 "
        "{%0,%1,%2,%3}, {%4,%5,%6,%7}, {%8,%9}, {%0,%1,%2,%3};"
        : "+f"(d0), "+f"(d1), "+f"(d2), "+f"(d3)
        : "r"(a0), "r"(a1), "r"(a2), "r"(a3), "r"(b0), "r"(b1));
}

__device__ __forceinline__ int get_label(const void* p, int i, int is64) {
    if (is64) return (int)(((const long long*)p)[i]);
    return ((const int*)p)[i];
}

// triangle flattening: strip i holds tiles (i, j=i..63)
__device__ __forceinline__ int strip_start(int i) { return i * 64 - (i * (i - 1)) / 2; }
__device__ __forceinline__ void decode_tile(int f, int& i, int& j) {
    int s = 0;
    while (s < 63 && strip_start(s + 1) <= f) s++;
    i = s;
    j = s + (f - strip_start(s));
}
__device__ __forceinline__ void step_tile(int& i, int& j) {
    j++;
    if (j == 64) { i++; j = i; }
}

// smem tile: 128 rows x 256B; 16B chunk c16 swizzled by row&7
__device__ __forceinline__ uint32_t tile_addr(uint32_t base, int row, int c16) {
    return base + (uint32_t)row * 256u + (uint32_t)(((c16 ^ (row & 7)) << 4));
}

// ---------------------------------------------------------------------------
// convert: fp32 emb -> prescaled fp16 (hi only), row-major
// ---------------------------------------------------------------------------
__global__ void __launch_bounds__(256)
convert_kernel(const float* __restrict__ emb)
{
    int f = blockIdx.x * 256 + threadIdx.x;   // 131072 chunks of 8 elements
    int r = f >> 4;
    int c8 = f & 15;
    const float4* src = (const float4*)(emb + (size_t)r * DIM + c8 * 8);
    float4 v0 = src[0], v1 = src[1];
    float a[8] = {v0.x, v0.y, v0.z, v0.w, v1.x, v1.y, v1.z, v1.w};

    uint32_t hi[4];
    #pragma unroll
    for (int p = 0; p < 4; p++) {
        __half h0 = __float2half_rn(a[2 * p] * SQRT_SCALE);
        __half h1 = __float2half_rn(a[2 * p + 1] * SQRT_SCALE);
        hi[p] = (uint32_t)__half_as_ushort(h0) | ((uint32_t)__half_as_ushort(h1) << 16);
    }
    *(uint4*)(g_hi + (size_t)r * DIM + c8 * 8) = make_uint4(hi[0], hi[1], hi[2], hi[3]);
}

// ---------------------------------------------------------------------------
// main MMA kernel
// ---------------------------------------------------------------------------
extern __shared__ __align__(16) char smem_dyn_c[];

// copy one 128x128 fp16 tile (rows grow0..+127) into swizzled smem image
__device__ __forceinline__ void stage_tile(uint32_t base, int grow0, int tid) {
    #pragma unroll
    for (int i = 0; i < 4; i++) {
        int f = tid + i * THREADS;          // 0..2047
        int row = f >> 4;
        int c16 = f & 15;
        cp16(tile_addr(base, row, c16), g_hi + (size_t)(grow0 + row) * DIM + c16 * 8);
    }
}

__global__ void __launch_bounds__(THREADS, 1)
contrastive_mma_kernel(const void* __restrict__ labels_raw)
{
    __shared__ int s_cl[2][BN];
    __shared__ int s_flag;
    __shared__ float2 s_rr[BM][4];
    __shared__ float2 s_cr[BN][4];

    const int tid = threadIdx.x;
    const int lane = tid & 31;
    const int wid = tid >> 5;
    const int c = blockIdx.x;

    uint32_t sbase = (smem_u32(smem_dyn_c) + 1023u) & ~1023u;
    const uint32_t Abase = sbase;
    const uint32_t Bbuf0 = sbase + 1u * PLANE;
    const uint32_t Bbuf1 = sbase + 2u * PLANE;

    if (tid == 0) {
        const int* li = (const int*)labels_raw;
        int is64 = 1;
        for (int i = 0; i < 64; i++)
            if (li[2 * i + 1] != 0) { is64 = 0; break; }
        s_flag = is64;
    }
    __syncthreads();
    const int is64 = s_flag;

    const int wm = wid >> 2;       // 0..3
    const int wn = wid & 3;        // 0..3
    const int m0 = wm * 32;
    const int n0 = wn * 32;
    const int g = lane >> 2;
    const int tig = lane & 3;

    // per-lane ldmatrix address components (formulas verified in R3-R6)
    const uint32_t aRowOff = (uint32_t)(m0 + (lane & 15)) * 256u;
    const int kh = lane >> 4;                                   // A k-half bit
    const uint32_t bRowSub = (uint32_t)((lane & 7) + ((lane >> 4) & 1) * 8);
    const int kb = (lane >> 3) & 1;                             // B k-half bit
    const int sx = lane & 7;                                    // swizzle xor

    // chunk of the flattened triangle
    const int f0 = (c * TOTTILES) / NCTA;
    const int f1 = ((c + 1) * TOTTILES) / NCTA;
    int ti, tj;
    decode_tile(f0, ti, tj);

    // row labels for current strip: rows m0 + mf*16 + g (+8)
    int rl[4];
    #pragma unroll
    for (int mf = 0; mf < 2; mf++) {
        rl[mf * 2]     = get_label(labels_raw, ti * BM + m0 + mf * 16 + g, is64);
        rl[mf * 2 + 1] = get_label(labels_raw, ti * BM + m0 + mf * 16 + g + 8, is64);
    }

    // prologue: A + B(f0) -> group 0; B(f0+1) -> group 1
    stage_tile(Abase, ti * BM, tid);
    stage_tile(Bbuf0, tj * BN, tid);
    CP_COMMIT();
    {
        int i1 = ti, j1 = tj;
        step_tile(i1, j1);
        if (f0 + 1 < f1) stage_tile(Bbuf1, j1 * BN, tid);
        CP_COMMIT();
    }

    for (int t = f0; t < f1; ++t) {
        const int cb = (t - f0) & 1;          // LOCAL parity
        const uint32_t Bb = cb ? Bbuf1 : Bbuf0;

        if (t > f0 && tj == ti) {
            // new strip: reload A + row labels
            __syncthreads();                  // everyone done with old A
            stage_tile(Abase, ti * BM, tid);
            #pragma unroll
            for (int mf = 0; mf < 2; mf++) {
                rl[mf * 2]     = get_label(labels_raw, ti * BM + m0 + mf * 16 + g, is64);
                rl[mf * 2 + 1] = get_label(labels_raw, ti * BM + m0 + mf * 16 + g + 8, is64);
            }
            CP_COMMIT();
            CP_WAIT0();                       // drain A + pending B
        } else {
            CP_WAIT1();                       // B(t) resident
        }

        if (tid < BN) s_cl[cb][tid] = get_label(labels_raw, tj * BN + tid, is64);
        __syncthreads();                      // B(t) + labels visible to all

        const int diag = (ti == tj);
        float rt[4], rp[4], ct[8], cp[8];
        #pragma unroll
        for (int i = 0; i < 4; i++) { rt[i] = 0.f; rp[i] = 0.f; }
        #pragma unroll
        for (int i = 0; i < 8; i++) { ct[i] = 0.f; cp[i] = 0.f; }

        // two n16-chunks: full-K MMA then immediate epilogue (cross-warp overlap)
        #pragma unroll
        for (int nc = 0; nc < 2; nc++) {
            const uint32_t bRowOff = (uint32_t)(n0 + nc * 16) * 256u + bRowSub * 256u;

            float acc[16];
            #pragma unroll
            for (int i = 0; i < 16; i++) acc[i] = 0.f;

            #pragma unroll
            for (int ks = 0; ks < 8; ks++) {
                uint32_t ac = (uint32_t)(((2 * ks + kh) ^ sx) << 4);
                uint32_t a0, a1, a2, a3, a4, a5, a6, a7;
                ldsm4(a0, a1, a2, a3, Abase + aRowOff + ac);           // mf=0
                ldsm4(a4, a5, a6, a7, Abase + aRowOff + 4096u + ac);   // mf=1

                uint32_t bc = (uint32_t)(((2 * ks + kb) ^ sx) << 4);
                uint32_t b0, b1, b2, b3;
                ldsm4(b0, b1, b2, b3, Bb + bRowOff + bc);

                mma16816(acc[0],  acc[1],  acc[2],  acc[3],  a0, a1, a2, a3, b0, b1);
                mma16816(acc[4],  acc[5],  acc[6],  acc[7],  a0, a1, a2, a3, b2, b3);
                mma16816(acc[8],  acc[9],  acc[10], acc[11], a4, a5, a6, a7, b0, b1);
                mma16816(acc[12], acc[13], acc[14], acc[15], a4, a5, a6, a7, b2, b3);
            }

            // epilogue for this chunk's 16 cols
            #pragma unroll
            for (int nf = 0; nf < 2; nf++) {
                const int lc0 = n0 + nc * 16 + nf * 8 + tig * 2;
                const int cl0 = s_cl[cb][lc0];
                const int cl1 = s_cl[cb][lc0 + 1];
                #pragma unroll
                for (int mf = 0; mf < 2; mf++) {
                    const int d = (mf * 2 + nf) * 4;
                    float e00 = ex2f(acc[d]);
                    float e01 = ex2f(acc[d + 1]);
                    float e10 = ex2f(acc[d + 2]);
                    float e11 = ex2f(acc[d + 3]);
                    if (diag) {
                        const int lr0 = m0 + mf * 16 + g;
                        const int lr1 = lr0 + 8;
                        if (lr0 == lc0)     e00 = 0.f;
                        if (lr0 == lc0 + 1) e01 = 0.f;
                        if (lr1 == lc0)     e10 = 0.f;
                        if (lr1 == lc0 + 1) e11 = 0.f;
                    }
                    float p00 = (cl0 == rl[mf * 2])     ? e00 : 0.f;
                    float p01 = (cl1 == rl[mf * 2])     ? e01 : 0.f;
                    float p10 = (cl0 == rl[mf * 2 + 1]) ? e10 : 0.f;
                    float p11 = (cl1 == rl[mf * 2 + 1]) ? e11 : 0.f;
                    rt[mf * 2]     += e00 + e01;
                    rt[mf * 2 + 1] += e10 + e11;
                    rp[mf * 2]     += p00 + p01;
                    rp[mf * 2 + 1] += p10 + p11;
                    const int ci = nc * 4 + nf * 2;
                    ct[ci]     += e00 + e10;
                    ct[ci + 1] += e01 + e11;
                    cp[ci]     += p00 + p10;
                    cp[ci + 1] += p01 + p11;
                }
            }
        }

        __syncthreads();                      // all warps done reading Bb
        {                                     // prefetch B(t+2) into freed buffer
            int i2 = ti, j2 = tj;
            step_tile(i2, j2);
            step_tile(i2, j2);
            if (t + 2 < f1) stage_tile(Bb, j2 * BN, tid);
            CP_COMMIT();                      // commit (possibly empty) group
        }

        // tail: shuffle reductions + smem partials
        #pragma unroll
        for (int i = 0; i < 4; i++) {         // rows: reduce over tig
            rt[i] += __shfl_xor_sync(0xFFFFFFFFu, rt[i], 1);
            rt[i] += __shfl_xor_sync(0xFFFFFFFFu, rt[i], 2);
            rp[i] += __shfl_xor_sync(0xFFFFFFFFu, rp[i], 1);
            rp[i] += __shfl_xor_sync(0xFFFFFFFFu, rp[i], 2);
        }
        #pragma unroll
        for (int i = 0; i < 8; i++) {         // cols: reduce over g
            ct[i] += __shfl_xor_sync(0xFFFFFFFFu, ct[i], 4);
            ct[i] += __shfl_xor_sync(0xFFFFFFFFu, ct[i], 8);
            ct[i] += __shfl_xor_sync(0xFFFFFFFFu, ct[i], 16);
            cp[i] += __shfl_xor_sync(0xFFFFFFFFu, cp[i], 4);
            cp[i] += __shfl_xor_sync(0xFFFFFFFFu, cp[i], 8);
            cp[i] += __shfl_xor_sync(0xFFFFFFFFu, cp[i], 16);
        }
        if (tig == 0) {
            #pragma unroll
            for (int mf = 0; mf < 2; mf++) {
                s_rr[m0 + mf * 16 + g][wn]     = make_float2(rt[mf * 2],     rp[mf * 2]);
                s_rr[m0 + mf * 16 + g + 8][wn] = make_float2(rt[mf * 2 + 1], rp[mf * 2 + 1]);
            }
        }
        if (lane < 4) {   // g==0 lanes hold col sums (butterfly result everywhere)
            #pragma unroll
            for (int nc = 0; nc < 2; nc++)
                #pragma unroll
                for (int nf = 0; nf < 2; nf++) {
                    const int ci = nc * 4 + nf * 2;
                    const int col = n0 + nc * 16 + nf * 8 + lane * 2;
                    s_cr[col][wm]     = make_float2(ct[ci],     cp[ci]);
                    s_cr[col + 1][wm] = make_float2(ct[ci + 1], cp[ci + 1]);
                }
        }
        __syncthreads();
        if (tid < BM) {
            float2 a0 = s_rr[tid][0], a1 = s_rr[tid][1], a2 = s_rr[tid][2], a3 = s_rr[tid][3];
            g_rpart[tj][ti * BM + tid] =
                make_float2(a0.x + a1.x + a2.x + a3.x, a0.y + a1.y + a2.y + a3.y);
        } else if (tid < 2 * BM) {
            const int cc = tid - BM;
            float2 a0 = s_cr[cc][0], a1 = s_cr[cc][1], a2 = s_cr[cc][2], a3 = s_cr[cc][3];
            g_cpart[ti][tj * BN + cc] =
                make_float2(a0.x + a1.x + a2.x + a3.x, a0.y + a1.y + a2.y + a3.y);
        }

        step_tile(ti, tj);
    }
}

// ---------------------------------------------------------------------------
// reduce + finalize
// ---------------------------------------------------------------------------
__global__ void __launch_bounds__(256)
reduce1_kernel()
{
    __shared__ float ws[8], wc[8];
    const int tid = threadIdx.x;
    const int r = blockIdx.x * 256 + tid;
    const int b = r >> 7;

    float tt = 0.f, pp = 0.f;
    for (int j = b; j < NBLK; j++) {
        float2 v = g_rpart[j][r];
        tt += v.x; pp += v.y;
    }
    for (int i = 0; i < b; i++) {
        float2 v = g_cpart[i][r];
        tt += v.x; pp += v.y;
    }

    float loss = 0.f, cnt = 0.f;
    if (pp > 0.f) {
        loss = -logf(pp / (tt + 1e-8f) + 1e-8f);
        cnt = 1.f;
    }
    #pragma unroll
    for (int o = 16; o > 0; o >>= 1) {
        loss += __shfl_xor_sync(0xFFFFFFFFu, loss, o);
        cnt  += __shfl_xor_sync(0xFFFFFFFFu, cnt, o);
    }
    if ((tid & 31) == 0) { ws[tid >> 5] = loss; wc[tid >> 5] = cnt; }
    __syncthreads();
    if (tid == 0) {
        float S = 0.f, C = 0.f;
        #pragma unroll
        for (int w = 0; w < 8; w++) { S += ws[w]; C += wc[w]; }
        g_part[0][blockIdx.x] = S;
        g_part[1][blockIdx.x] = C;
    }
}

__global__ void __launch_bounds__(32)
reduce2_kernel(float* __restrict__ out)
{
    const int tid = threadIdx.x;
    float S = g_part[0][tid];
    float C = g_part[1][tid];
    #pragma unroll
    for (int o = 16; o > 0; o >>= 1) {
        S += __shfl_xor_sync(0xFFFFFFFFu, S, o);
        C += __shfl_xor_sync(0xFFFFFFFFu, C, o);
    }
    if (tid == 0) out[0] = (C > 0.f) ? S / fmaxf(C, 1.f) : 0.f;
}

// ---------------------------------------------------------------------------
extern "C" void kernel_launch(void* const* d_in, const int* in_sizes, int n_in,
                              void* d_out, int out_size)
{
    const float* emb = (const float*)d_in[0];
    const void* labels = d_in[1];
    float* out = (float*)d_out;

    const int dyn_smem = 1024 + 3 * PLANE;   // pad + A + 2x B (hi planes only)
    cudaFuncSetAttribute(contrastive_mma_kernel,
                         cudaFuncAttributeMaxDynamicSharedMemorySize, dyn_smem);

    convert_kernel<<<512, 256>>>(emb);
    contrastive_mma_kernel<<<NCTA, THREADS, dyn_smem>>>(labels);
    reduce1_kernel<<<32, 256>>>();
    reduce2_kernel<<<1, 32>>>(out);
}

// round 8
// speedup vs baseline: 8.6475x; 1.2026x over previous
#include <cuda_runtime.h>
#include <cuda_fp16.h>
#include <cstdint>

// ============================================================================
// ContrastiveLoss, single-pass fp16 mma.sync GEMM, upper triangle only.
// R8: 256 threads / 8 warps, warp tile 64x32 chunked over m (2x 32x32).
// Smem operand traffic = 256 KB/tile = 2048 cyc = HMMA floor (R7 was
// 384 KB -> smem-bound at 3072). Chunked epilogue overlaps MUFU with the
// sibling warp's MMA. Merged finalize kernel (one launch less).
// Deterministic: per-tile slot writes unique, fixed-order reductions.
// ============================================================================

#define N_ROWS 8192
#define DIM    128
#define BM     128
#define BN     128
#define NBLK   64
#define TOTTILES 2080        // NBLK*(NBLK+1)/2
#define NCTA   148
#define THREADS 256
#define PLANE  32768         // one 128x128 fp16 plane

// sqrt(log2(e)/0.07): folded into BOTH operands so acc == (log2e/T) * dot
#define SQRT_SCALE 4.53981642f

// ---------------------------------------------------------------------------
__device__ float2 g_rpart[NBLK][N_ROWS];   // tile (i,j): rows -> [j][i*128+r]
__device__ float2 g_cpart[NBLK][N_ROWS];   // tile (i,j): cols -> [i][j*128+c]
__device__ float g_fpart[2][32];
__device__ unsigned int g_ctr = 0;
__device__ __align__(16) __half g_hi[N_ROWS * DIM];

// ---------------------------------------------------------------------------
__device__ __forceinline__ uint32_t smem_u32(const void* p) {
    uint32_t a;
    asm("{ .reg .u64 t; cvta.to.shared.u64 t, %1; cvt.u32.u64 %0, t; }"
        : "=r"(a) : "l"(p));
    return a;
}

__device__ __forceinline__ float ex2f(float x) {
    float y;
    asm("ex2.approx.ftz.f32 %0, %1;" : "=f"(y) : "f"(x));
    return y;
}

__device__ __forceinline__ void cp16(uint32_t dst, const void* src) {
    asm volatile("cp.async.cg.shared.global [%0], [%1], 16;"
                 :: "r"(dst), "l"(src) : "memory");
}
#define CP_COMMIT() asm volatile("cp.async.commit_group;" ::: "memory")
#define CP_WAIT0()  asm volatile("cp.async.wait_group 0;" ::: "memory")
#define CP_WAIT1()  asm volatile("cp.async.wait_group 1;" ::: "memory")

__device__ __forceinline__ void ldsm4(uint32_t& r0, uint32_t& r1,
                                      uint32_t& r2, uint32_t& r3, uint32_t a) {
    asm volatile("ldmatrix.sync.aligned.m8n8.x4.shared.b16 {%0,%1,%2,%3}, [%4];"
                 : "=r"(r0), "=r"(r1), "=r"(r2), "=r"(r3) : "r"(a));
}

__device__ __forceinline__ void mma16816(float& d0, float& d1, float& d2, float& d3,
                                         uint32_t a0, uint32_t a1, uint32_t a2, uint32_t a3,
                                         uint32_t b0, uint32_t b1) {
    asm volatile(
        "mma.sync.aligned.m16n8k16.row.col.f32.f16.f16.f32 "
        "{%0,%1,%2,%3}, {%4,%5,%6,%7}, {%8,%9}, {%0,%1,%2,%3};"
        : "+f"(d0), "+f"(d1), "+f"(d2), "+f"(d3)
        : "r"(a0), "r"(a1), "r"(a2), "r"(a3), "r"(b0), "r"(b1));
}

__device__ __forceinline__ int get_label(const void* p, int i, int is64) {
    if (is64) return (int)(((const long long*)p)[i]);
    return ((const int*)p)[i];
}

// triangle flattening: strip i holds tiles (i, j=i..63)
__device__ __forceinline__ int strip_start(int i) { return i * 64 - (i * (i - 1)) / 2; }
__device__ __forceinline__ void decode_tile(int f, int& i, int& j) {
    int s = 0;
    while (s < 63 && strip_start(s + 1) <= f) s++;
    i = s;
    j = s + (f - strip_start(s));
}
__device__ __forceinline__ void step_tile(int& i, int& j) {
    j++;
    if (j == 64) { i++; j = i; }
}

// smem tile: 128 rows x 256B; 16B chunk c16 swizzled by row&7
__device__ __forceinline__ uint32_t tile_addr(uint32_t base, int row, int c16) {
    return base + (uint32_t)row * 256u + (uint32_t)(((c16 ^ (row & 7)) << 4));
}

// ---------------------------------------------------------------------------
// convert: fp32 emb -> prescaled fp16, row-major
// ---------------------------------------------------------------------------
__global__ void __launch_bounds__(256)
convert_kernel(const float* __restrict__ emb)
{
    int f = blockIdx.x * 256 + threadIdx.x;   // 131072 chunks of 8 elements
    int r = f >> 4;
    int c8 = f & 15;
    const float4* src = (const float4*)(emb + (size_t)r * DIM + c8 * 8);
    float4 v0 = src[0], v1 = src[1];
    float a[8] = {v0.x, v0.y, v0.z, v0.w, v1.x, v1.y, v1.z, v1.w};

    uint32_t hi[4];
    #pragma unroll
    for (int p = 0; p < 4; p++) {
        __half h0 = __float2half_rn(a[2 * p] * SQRT_SCALE);
        __half h1 = __float2half_rn(a[2 * p + 1] * SQRT_SCALE);
        hi[p] = (uint32_t)__half_as_ushort(h0) | ((uint32_t)__half_as_ushort(h1) << 16);
    }
    *(uint4*)(g_hi + (size_t)r * DIM + c8 * 8) = make_uint4(hi[0], hi[1], hi[2], hi[3]);
}

// ---------------------------------------------------------------------------
// main MMA kernel
// ---------------------------------------------------------------------------
extern __shared__ __align__(16) char smem_dyn_c[];

// copy one 128x128 fp16 tile (rows grow0..+127) into swizzled smem image
__device__ __forceinline__ void stage_tile(uint32_t base, int grow0, int tid) {
    #pragma unroll
    for (int i = 0; i < 8; i++) {
        int f = tid + i * THREADS;          // 0..2047
        int row = f >> 4;
        int c16 = f & 15;
        cp16(tile_addr(base, row, c16), g_hi + (size_t)(grow0 + row) * DIM + c16 * 8);
    }
}

__global__ void __launch_bounds__(THREADS, 1)
contrastive_mma_kernel(const void* __restrict__ labels_raw)
{
    __shared__ int s_cl[2][BN];
    __shared__ int s_flag;
    __shared__ float2 s_rr[BM][4];
    __shared__ float2 s_cr[BN][2];

    const int tid = threadIdx.x;
    const int lane = tid & 31;
    const int wid = tid >> 5;
    const int c = blockIdx.x;

    uint32_t sbase = (smem_u32(smem_dyn_c) + 1023u) & ~1023u;
    const uint32_t Abase = sbase;
    const uint32_t Bbuf0 = sbase + 1u * PLANE;
    const uint32_t Bbuf1 = sbase + 2u * PLANE;

    if (tid == 0) {
        const int* li = (const int*)labels_raw;
        int is64 = 1;
        for (int i = 0; i < 64; i++)
            if (li[2 * i + 1] != 0) { is64 = 0; break; }
        s_flag = is64;
    }
    __syncthreads();
    const int is64 = s_flag;

    const int wm = wid >> 2;       // 0..1
    const int wn = wid & 3;        // 0..3
    const int m0 = wm * 64;
    const int n0 = wn * 32;
    const int g = lane >> 2;
    const int tig = lane & 3;

    // per-lane ldmatrix address components (formulas verified in R3-R7)
    const uint32_t aRowOff = (uint32_t)(m0 + (lane & 15)) * 256u;
    const int kh = lane >> 4;                                   // A k-half bit
    const uint32_t bRowOff = (uint32_t)(n0 + (lane & 7) + ((lane >> 4) & 1) * 8) * 256u;
    const int kb = (lane >> 3) & 1;                             // B k-half bit
    const int sx = lane & 7;                                    // swizzle xor

    // chunk of the flattened triangle
    const int f0 = (c * TOTTILES) / NCTA;
    const int f1 = ((c + 1) * TOTTILES) / NCTA;
    int ti, tj;
    decode_tile(f0, ti, tj);

    // row labels: rows m0 + mc*32 + mfl*16 + g (+8), index mc*4 + mfl*2 + {0,1}
    int rl[8];
    #pragma unroll
    for (int mc = 0; mc < 2; mc++)
        #pragma unroll
        for (int mfl = 0; mfl < 2; mfl++) {
            rl[mc * 4 + mfl * 2]     = get_label(labels_raw, ti * BM + m0 + mc * 32 + mfl * 16 + g, is64);
            rl[mc * 4 + mfl * 2 + 1] = get_label(labels_raw, ti * BM + m0 + mc * 32 + mfl * 16 + g + 8, is64);
        }

    // prologue: A + B(f0) -> group 0; B(f0+1) -> group 1
    stage_tile(Abase, ti * BM, tid);
    stage_tile(Bbuf0, tj * BN, tid);
    CP_COMMIT();
    {
        int i1 = ti, j1 = tj;
        step_tile(i1, j1);
        if (f0 + 1 < f1) stage_tile(Bbuf1, j1 * BN, tid);
        CP_COMMIT();
    }

    for (int t = f0; t < f1; ++t) {
        const int cb = (t - f0) & 1;          // LOCAL parity
        const uint32_t Bb = cb ? Bbuf1 : Bbuf0;

        if (t > f0 && tj == ti) {
            // new strip: reload A + row labels
            __syncthreads();                  // everyone done with old A
            stage_tile(Abase, ti * BM, tid);
            #pragma unroll
            for (int mc = 0; mc < 2; mc++)
                #pragma unroll
                for (int mfl = 0; mfl < 2; mfl++) {
                    rl[mc * 4 + mfl * 2]     = get_label(labels_raw, ti * BM + m0 + mc * 32 + mfl * 16 + g, is64);
                    rl[mc * 4 + mfl * 2 + 1] = get_label(labels_raw, ti * BM + m0 + mc * 32 + mfl * 16 + g + 8, is64);
                }
            CP_COMMIT();
            CP_WAIT0();                       // drain A + pending B
        } else {
            CP_WAIT1();                       // B(t) resident
        }

        if (tid < BN) s_cl[cb][tid] = get_label(labels_raw, tj * BN + tid, is64);
        __syncthreads();                      // B(t) + labels visible to all

        const int diag = (ti == tj);
        float rt[8], rp[8], ct[8], cp[8];
        #pragma unroll
        for (int i = 0; i < 8; i++) { rt[i] = 0.f; rp[i] = 0.f; ct[i] = 0.f; cp[i] = 0.f; }

        // two m-chunks (32x32 each): full-K MMA then immediate epilogue
        #pragma unroll
        for (int mc = 0; mc < 2; mc++) {
            const uint32_t aChunk = Abase + aRowOff + (uint32_t)(mc * 8192);

            float acc[32];
            #pragma unroll
            for (int i = 0; i < 32; i++) acc[i] = 0.f;

            #pragma unroll
            for (int ks = 0; ks < 8; ks++) {
                uint32_t ac = (uint32_t)(((2 * ks + kh) ^ sx) << 4);
                uint32_t a0, a1, a2, a3, a4, a5, a6, a7;
                ldsm4(a0, a1, a2, a3, aChunk + ac);            // rows +0..15
                ldsm4(a4, a5, a6, a7, aChunk + 4096u + ac);    // rows +16..31

                uint32_t bc = (uint32_t)(((2 * ks + kb) ^ sx) << 4);
                uint32_t b[8];
                ldsm4(b[0], b[1], b[2], b[3], Bb + bRowOff + bc);           // cols n0..+15
                ldsm4(b[4], b[5], b[6], b[7], Bb + bRowOff + 4096u + bc);   // cols +16..31

                #pragma unroll
                for (int nf = 0; nf < 4; nf++) {
                    mma16816(acc[nf * 4],     acc[nf * 4 + 1], acc[nf * 4 + 2], acc[nf * 4 + 3],
                             a0, a1, a2, a3, b[nf * 2], b[nf * 2 + 1]);
                    mma16816(acc[16 + nf * 4], acc[16 + nf * 4 + 1], acc[16 + nf * 4 + 2], acc[16 + nf * 4 + 3],
                             a4, a5, a6, a7, b[nf * 2], b[nf * 2 + 1]);
                }
            }

            // epilogue for this chunk (rows m0+mc*32 .. +31, cols n0..+31)
            #pragma unroll
            for (int nf = 0; nf < 4; nf++) {
                const int lc0 = n0 + nf * 8 + tig * 2;
                const int cl0 = s_cl[cb][lc0];
                const int cl1 = s_cl[cb][lc0 + 1];
                #pragma unroll
                for (int mfl = 0; mfl < 2; mfl++) {
                    const int d = mfl * 16 + nf * 4;
                    float e00 = ex2f(acc[d]);
                    float e01 = ex2f(acc[d + 1]);
                    float e10 = ex2f(acc[d + 2]);
                    float e11 = ex2f(acc[d + 3]);
                    if (diag) {
                        const int lr0 = m0 + mc * 32 + mfl * 16 + g;
                        const int lr1 = lr0 + 8;
                        if (lr0 == lc0)     e00 = 0.f;
                        if (lr0 == lc0 + 1) e01 = 0.f;
                        if (lr1 == lc0)     e10 = 0.f;
                        if (lr1 == lc0 + 1) e11 = 0.f;
                    }
                    const int ri = mc * 4 + mfl * 2;
                    float p00 = (cl0 == rl[ri])     ? e00 : 0.f;
                    float p01 = (cl1 == rl[ri])     ? e01 : 0.f;
                    float p10 = (cl0 == rl[ri + 1]) ? e10 : 0.f;
                    float p11 = (cl1 == rl[ri + 1]) ? e11 : 0.f;
                    rt[ri]     += e00 + e01;
                    rt[ri + 1] += e10 + e11;
                    rp[ri]     += p00 + p01;
                    rp[ri + 1] += p10 + p11;
                    ct[nf * 2]     += e00 + e10;
                    ct[nf * 2 + 1] += e01 + e11;
                    cp[nf * 2]     += p00 + p10;
                    cp[nf * 2 + 1] += p01 + p11;
                }
            }
        }

        __syncthreads();                      // all warps done reading Bb
        {                                     // prefetch B(t+2) into freed buffer
            int i2 = ti, j2 = tj;
            step_tile(i2, j2);
            step_tile(i2, j2);
            if (t + 2 < f1) stage_tile(Bb, j2 * BN, tid);
            CP_COMMIT();                      // commit (possibly empty) group
        }

        // tail: shuffle reductions + smem partials
        #pragma unroll
        for (int i = 0; i < 8; i++) {         // rows: reduce over tig
            rt[i] += __shfl_xor_sync(0xFFFFFFFFu, rt[i], 1);
            rt[i] += __shfl_xor_sync(0xFFFFFFFFu, rt[i], 2);
            rp[i] += __shfl_xor_sync(0xFFFFFFFFu, rp[i], 1);
            rp[i] += __shfl_xor_sync(0xFFFFFFFFu, rp[i], 2);
        }
        #pragma unroll
        for (int i = 0; i < 8; i++) {         // cols: reduce over g
            ct[i] += __shfl_xor_sync(0xFFFFFFFFu, ct[i], 4);
            ct[i] += __shfl_xor_sync(0xFFFFFFFFu, ct[i], 8);
            ct[i] += __shfl_xor_sync(0xFFFFFFFFu, ct[i], 16);
            cp[i] += __shfl_xor_sync(0xFFFFFFFFu, cp[i], 4);
            cp[i] += __shfl_xor_sync(0xFFFFFFFFu, cp[i], 8);
            cp[i] += __shfl_xor_sync(0xFFFFFFFFu, cp[i], 16);
        }
        if (tig == 0) {
            #pragma unroll
            for (int mc = 0; mc < 2; mc++)
                #pragma unroll
                for (int mfl = 0; mfl < 2; mfl++) {
                    const int ri = mc * 4 + mfl * 2;
                    const int row = m0 + mc * 32 + mfl * 16 + g;
                    s_rr[row][wn]     = make_float2(rt[ri],     rp[ri]);
                    s_rr[row + 8][wn] = make_float2(rt[ri + 1], rp[ri + 1]);
                }
        }
        if (lane < 4) {   // g==0 lanes carry col sums (butterfly leaves result everywhere)
            #pragma unroll
            for (int nf = 0; nf < 4; nf++) {
                const int col = n0 + nf * 8 + lane * 2;
                s_cr[col][wm]     = make_float2(ct[nf * 2],     cp[nf * 2]);
                s_cr[col + 1][wm] = make_float2(ct[nf * 2 + 1], cp[nf * 2 + 1]);
            }
        }
        __syncthreads();
        if (tid < BM) {
            float2 a0 = s_rr[tid][0], a1 = s_rr[tid][1], a2 = s_rr[tid][2], a3 = s_rr[tid][3];
            g_rpart[tj][ti * BM + tid] =
                make_float2(a0.x + a1.x + a2.x + a3.x, a0.y + a1.y + a2.y + a3.y);
        } else {
            const int cc = tid - BM;
            float2 a0 = s_cr[cc][0], a1 = s_cr[cc][1];
            g_cpart[ti][tj * BN + cc] = make_float2(a0.x + a1.x, a0.y + a1.y);
        }

        step_tile(ti, tj);
    }
}

// ---------------------------------------------------------------------------
// merged finalize: 32 blocks; last block reduces the 32 partials
// ---------------------------------------------------------------------------
__global__ void __launch_bounds__(256)
finalize_kernel(float* __restrict__ out)
{
    __shared__ float ws[8], wc[8];
    __shared__ int s_last;
    const int tid = threadIdx.x;
    const int r = blockIdx.x * 256 + tid;
    const int b = r >> 7;

    float tt = 0.f, pp = 0.f;
    for (int j = b; j < NBLK; j++) {
        float2 v = g_rpart[j][r];
        tt += v.x; pp += v.y;
    }
    for (int i = 0; i < b; i++) {
        float2 v = g_cpart[i][r];
        tt += v.x; pp += v.y;
    }

    float loss = 0.f, cnt = 0.f;
    if (pp > 0.f) {
        loss = -logf(pp / (tt + 1e-8f) + 1e-8f);
        cnt = 1.f;
    }
    #pragma unroll
    for (int o = 16; o > 0; o >>= 1) {
        loss += __shfl_xor_sync(0xFFFFFFFFu, loss, o);
        cnt  += __shfl_xor_sync(0xFFFFFFFFu, cnt, o);
    }
    if ((tid & 31) == 0) { ws[tid >> 5] = loss; wc[tid >> 5] = cnt; }
    __syncthreads();
    if (tid == 0) {
        float S = 0.f, C = 0.f;
        #pragma unroll
        for (int w = 0; w < 8; w++) { S += ws[w]; C += wc[w]; }
        g_fpart[0][blockIdx.x] = S;
        g_fpart[1][blockIdx.x] = C;
        __threadfence();
        unsigned int v = atomicInc(&g_ctr, 31u);   // wraps to 0 on the last block
        s_last = (v == 31u);
    }
    __syncthreads();
    if (s_last && tid < 32) {
        float S = g_fpart[0][tid];
        float C = g_fpart[1][tid];
        #pragma unroll
        for (int o = 16; o > 0; o >>= 1) {
            S += __shfl_xor_sync(0xFFFFFFFFu, S, o);
            C += __shfl_xor_sync(0xFFFFFFFFu, C, o);
        }
        if (tid == 0) out[0] = (C > 0.f) ? S / fmaxf(C, 1.f) : 0.f;
    }
}

// ---------------------------------------------------------------------------
extern "C" void kernel_launch(void* const* d_in, const int* in_sizes, int n_in,
                              void* d_out, int out_size)
{
    const float* emb = (const float*)d_in[0];
    const void* labels = d_in[1];
    float* out = (float*)d_out;

    const int dyn_smem = 1024 + 3 * PLANE;   // pad + A + 2x B
    cudaFuncSetAttribute(contrastive_mma_kernel,
                         cudaFuncAttributeMaxDynamicSharedMemorySize, dyn_smem);

    convert_kernel<<<512, 256>>>(emb);
    contrastive_mma_kernel<<<NCTA, THREADS, dyn_smem>>>(labels);
    finalize_kernel<<<32, 256>>>(out);
}